// round 5
// baseline (speedup 1.0000x reference)
#include <cuda_runtime.h>
#include <cstdint>

#define N_NODES 50000
#define N_EDGES 800000

// ---------------- scratch (no allocation allowed; 16B aligned) ----------------
__device__ __align__(16) float g_yz1[N_NODES * 256];   // [y1 = x@W1l | z1 = x@W1r]
__device__ __align__(16) float g_h1 [N_NODES * 128];   // relu hidden
__device__ __align__(16) float g_yz2[N_NODES * 64];    // [y2 = h1@W2l | z2 = h1@W2r]
__device__ __align__(16) float g_W1 [128 * 256];       // [W1l | W1r], K x 256
__device__ __align__(16) float g_W2 [128 * 64];        // [W2l | W2r], K x 64
__device__ __align__(16) int   g_src  [N_EDGES];       // normalized edge sources
__device__ __align__(16) int   g_dst  [N_EDGES];       // normalized edge dests
__device__ __align__(16) int   g_deg  [N_NODES];       // in-degree
__device__ __align__(16) int   g_start[N_NODES];       // CSR row starts (exclusive scan)
__device__ __align__(16) int   g_fill [N_NODES];       // fill cursors
__device__ __align__(16) int   g_csr  [N_EDGES];       // src per incoming edge, grouped by dst
__device__ int g_is64;                                  // edge_index dtype flag

// ---------------- dtype detect: int64 vs int32 edge_index -------------------
// Only reads int64 words with index < N_EDGES: byte range 6.4MB, in-bounds for
// BOTH interpretations (int32 buffer is exactly 2*N_EDGES*4 = 6.4MB).
__global__ void detect_kernel(const void* ei) {
    if (blockIdx.x | threadIdx.x) return;
    const long long* p = (const long long*)ei;
    int ok = 1;
    const int stride = N_EDGES / 64;
#pragma unroll 1
    for (int i = 0; i < 64; i++) {
        long long v = p[i * stride];
        if (v < 0 || v >= N_NODES) { ok = 0; break; }
    }
    g_is64 = ok;
}

// ---------------- normalize edges + zero int scratch -------------------------
__global__ void convert_kernel(const void* ei) {
    int e = blockIdx.x * blockDim.x + threadIdx.x;
    if (e < N_NODES) { g_deg[e] = 0; g_fill[e] = 0; }
    if (e >= N_EDGES) return;
    int s, d;
    if (g_is64) {
        const long long* p = (const long long*)ei;
        s = (int)p[e]; d = (int)p[N_EDGES + e];
    } else {
        const int* p = (const int*)ei;
        s = p[e]; d = p[N_EDGES + e];
    }
    // clamp defensively (garbage would trap the whole run)
    s = min(max(s, 0), N_NODES - 1);
    d = min(max(d, 0), N_NODES - 1);
    g_src[e] = s;
    g_dst[e] = d;
}

// ---------------- weight packing ----------------
__global__ void pack_weights(const float* __restrict__ W1l, const float* __restrict__ W1r,
                             const float* __restrict__ W2l, const float* __restrict__ W2r) {
    int tid = blockIdx.x * blockDim.x + threadIdx.x;
    if (tid < 128 * 256) {
        int k = tid >> 8, n = tid & 255;
        g_W1[tid] = (n < 128) ? W1l[k * 128 + n] : W1r[k * 128 + (n - 128)];
    }
    if (tid < 128 * 64) {
        int k = tid >> 6, n = tid & 63;
        g_W2[tid] = (n < 32) ? W2l[k * 32 + n] : W2r[k * 32 + (n - 32)];
    }
}

// ---------------- degree count (int atomics) ----------------
__global__ void count_kernel() {
    int e = blockIdx.x * blockDim.x + threadIdx.x;
    if (e < N_EDGES) atomicAdd(&g_deg[g_dst[e]], 1);
}

// ---------------- exclusive scan of g_deg -> g_start (1 block) ----------------
__global__ void __launch_bounds__(1024) scan_kernel() {
    __shared__ int wsum[32];
    __shared__ int carry_sh;
    int tid = threadIdx.x, lane = tid & 31, wid = tid >> 5;
    if (tid == 0) carry_sh = 0;
    __syncthreads();
    for (int base = 0; base < N_NODES; base += 1024) {
        int i = base + tid;
        int v = (i < N_NODES) ? g_deg[i] : 0;
        int inc = v;
#pragma unroll
        for (int o = 1; o < 32; o <<= 1) {
            int t = __shfl_up_sync(0xFFFFFFFFu, inc, o);
            if (lane >= o) inc += t;
        }
        if (lane == 31) wsum[wid] = inc;
        __syncthreads();
        if (wid == 0) {
            int s = wsum[lane];
#pragma unroll
            for (int o = 1; o < 32; o <<= 1) {
                int t = __shfl_up_sync(0xFFFFFFFFu, s, o);
                if (lane >= o) s += t;
            }
            wsum[lane] = s;
        }
        __syncthreads();
        int woff = wid ? wsum[wid - 1] : 0;
        if (i < N_NODES) g_start[i] = carry_sh + woff + inc - v;
        __syncthreads();
        if (tid == 1023) carry_sh += woff + inc;   // carry + chunk total
        __syncthreads();
    }
}

// ---------------- CSR fill (int atomics) ----------------
__global__ void fill_kernel() {
    int e = blockIdx.x * blockDim.x + threadIdx.x;
    if (e >= N_EDGES) return;
    int dst = g_dst[e];
    int pos = g_start[dst] + atomicAdd(&g_fill[dst], 1);
    g_csr[pos] = g_src[e];
}

// ---------------- tiled SGEMM, K fixed = 128 ----------------
// C[M x N] = A[M x 128] @ B[128 x N].  BM=128, BK=16, 256 threads, TM=8.
template <int BN, int TN>
__global__ void __launch_bounds__(256)
sgemm_k128(const float* __restrict__ A, const float* __restrict__ B,
           float* __restrict__ C, int M, int N) {
    constexpr int BM = 128, BK = 16, TM = 8;
    __shared__ float As[BK][BM];
    __shared__ float Bs[BK][BN];

    const int tid = threadIdx.x;
    const int tx  = tid % (BN / TN);
    const int ty  = tid / (BN / TN);
    const int mBase = blockIdx.x * BM;
    const int nBase = blockIdx.y * BN;

    float acc[TM][TN];
#pragma unroll
    for (int m = 0; m < TM; m++)
#pragma unroll
        for (int n = 0; n < TN; n++) acc[m][n] = 0.f;

    for (int k0 = 0; k0 < 128; k0 += BK) {
#pragma unroll
        for (int it = 0; it < (BM * BK / 4) / 256; it++) {
            int idx = tid + it * 256;
            int row = idx >> 2, c4 = idx & 3;
            float4 v = make_float4(0.f, 0.f, 0.f, 0.f);
            int gr = mBase + row;
            if (gr < M) v = *(const float4*)(A + (size_t)gr * 128 + k0 + c4 * 4);
            As[c4 * 4 + 0][row] = v.x;
            As[c4 * 4 + 1][row] = v.y;
            As[c4 * 4 + 2][row] = v.z;
            As[c4 * 4 + 3][row] = v.w;
        }
#pragma unroll
        for (int it = 0; it < (BK * BN / 4) / 256; it++) {
            int idx = tid + it * 256;
            int row = idx / (BN / 4), c4 = idx % (BN / 4);
            *(float4*)(&Bs[row][c4 * 4]) =
                *(const float4*)(B + (size_t)(k0 + row) * N + nBase + c4 * 4);
        }
        __syncthreads();

#pragma unroll
        for (int kk = 0; kk < BK; kk++) {
            float a[TM], b[TN];
#pragma unroll
            for (int m = 0; m < TM; m++) a[m] = As[kk][ty * TM + m];
#pragma unroll
            for (int n = 0; n < TN; n++) b[n] = Bs[kk][tx * TN + n];
#pragma unroll
            for (int m = 0; m < TM; m++)
#pragma unroll
                for (int n = 0; n < TN; n++) acc[m][n] += a[m] * b[n];
        }
        __syncthreads();
    }

#pragma unroll
    for (int m = 0; m < TM; m++) {
        int gr = mBase + ty * TM + m;
        if (gr >= M) continue;
#pragma unroll
        for (int n = 0; n < TN; n += 4) {
            float4 v = make_float4(acc[m][n], acc[m][n + 1], acc[m][n + 2], acc[m][n + 3]);
            *(float4*)(C + (size_t)gr * N + nBase + tx * TN + n) = v;
        }
    }
}

// ---------------- layer-1 gather + epilogue: h1 = relu(mean(y1[src]) + z1 + b1) ----
__global__ void gather1_kernel(const float* __restrict__ b1) {
    int node = (blockIdx.x * blockDim.x + threadIdx.x) >> 5;  // warp per node
    if (node >= N_NODES) return;
    int lane = threadIdx.x & 31;

    int start = g_start[node];
    int deg   = g_deg[node];

    float4 acc = make_float4(0.f, 0.f, 0.f, 0.f);
    for (int e0 = 0; e0 < deg; e0 += 32) {
        int m = min(32, deg - e0);
        int myidx = e0 + lane;
        int s = (myidx < deg) ? g_csr[start + myidx] : 0;
        for (int j = 0; j < m; j++) {
            int src = __shfl_sync(0xFFFFFFFFu, s, j);
            float4 v = ((const float4*)g_yz1)[(size_t)src * 64 + lane];  // y1 row
            acc.x += v.x; acc.y += v.y; acc.z += v.z; acc.w += v.w;
        }
    }
    float inv = (deg > 0) ? 1.0f / (float)deg : 0.0f;
    float4 z  = ((const float4*)g_yz1)[(size_t)node * 64 + 32 + lane];   // z1 row
    float4 bb = ((const float4*)b1)[lane];
    float4 r;
    r.x = fmaxf(fmaf(acc.x, inv, z.x + bb.x), 0.f);
    r.y = fmaxf(fmaf(acc.y, inv, z.y + bb.y), 0.f);
    r.z = fmaxf(fmaf(acc.z, inv, z.z + bb.z), 0.f);
    r.w = fmaxf(fmaf(acc.w, inv, z.w + bb.w), 0.f);
    ((float4*)g_h1)[(size_t)node * 32 + lane] = r;
}

// ---------------- layer-2 gather + log_softmax, fully fused ----------------
__global__ void gather2_kernel(const float* __restrict__ b2, float* __restrict__ out) {
    int node = (blockIdx.x * blockDim.x + threadIdx.x) >> 5;  // warp per node
    if (node >= N_NODES) return;
    int lane = threadIdx.x & 31;                               // = output channel

    int start = g_start[node];
    int deg   = g_deg[node];

    float acc = 0.f;
    for (int e0 = 0; e0 < deg; e0 += 32) {
        int m = min(32, deg - e0);
        int myidx = e0 + lane;
        int s = (myidx < deg) ? g_csr[start + myidx] : 0;
        for (int j = 0; j < m; j++) {
            int src = __shfl_sync(0xFFFFFFFFu, s, j);
            acc += g_yz2[(size_t)src * 64 + lane];             // y2 row, coalesced 128B
        }
    }
    float inv = (deg > 0) ? 1.0f / (float)deg : 0.0f;
    float v = fmaf(acc, inv, g_yz2[(size_t)node * 64 + 32 + lane] + b2[lane]);

    float mx = v;
#pragma unroll
    for (int o = 16; o > 0; o >>= 1) mx = fmaxf(mx, __shfl_xor_sync(0xFFFFFFFFu, mx, o));
    float ex = expf(v - mx);
    float s = ex;
#pragma unroll
    for (int o = 16; o > 0; o >>= 1) s += __shfl_xor_sync(0xFFFFFFFFu, s, o);
    out[(size_t)node * 32 + lane] = v - mx - logf(s);
}

// ---------------- launch ----------------
extern "C" void kernel_launch(void* const* d_in, const int* in_sizes, int n_in,
                              void* d_out, int out_size) {
    const float* x   = (const float*)d_in[0];
    const void*  ei  = d_in[1];
    const float* W1l = (const float*)d_in[2];
    const float* W1r = (const float*)d_in[3];
    const float* b1  = (const float*)d_in[4];
    const float* W2l = (const float*)d_in[5];
    const float* W2r = (const float*)d_in[6];
    const float* b2  = (const float*)d_in[7];
    float* out = (float*)d_out;

    float *p_yz1, *p_h1, *p_yz2, *p_W1, *p_W2;
    cudaGetSymbolAddress((void**)&p_yz1, g_yz1);
    cudaGetSymbolAddress((void**)&p_h1,  g_h1);
    cudaGetSymbolAddress((void**)&p_yz2, g_yz2);
    cudaGetSymbolAddress((void**)&p_W1,  g_W1);
    cudaGetSymbolAddress((void**)&p_W2,  g_W2);

    detect_kernel<<<1, 32>>>(ei);
    convert_kernel<<<(N_EDGES + 255) / 256, 256>>>(ei);
    pack_weights<<<128, 256>>>(W1l, W1r, W2l, W2r);
    count_kernel<<<(N_EDGES + 255) / 256, 256>>>();
    scan_kernel<<<1, 1024>>>();
    fill_kernel<<<(N_EDGES + 255) / 256, 256>>>();

    // yz1 = x @ [W1l | W1r]   (M=50000, K=128, N=256)
    {
        dim3 grid((N_NODES + 127) / 128, 2);
        sgemm_k128<128, 8><<<grid, 256>>>(x, p_W1, p_yz1, N_NODES, 256);
    }
    gather1_kernel<<<(N_NODES * 32 + 255) / 256, 256>>>(b1);

    // yz2 = h1 @ [W2l | W2r]  (M=50000, K=128, N=64)
    {
        dim3 grid((N_NODES + 127) / 128, 1);
        sgemm_k128<64, 4><<<grid, 256>>>(p_h1, p_W2, p_yz2, N_NODES, 64);
    }
    gather2_kernel<<<(N_NODES * 32 + 255) / 256, 256>>>(b2, out);
}

// round 6
// speedup vs baseline: 1.0549x; 1.0549x over previous
#include <cuda_runtime.h>
#include <cstdint>

#define N_NODES 50000
#define N_EDGES 800000

// ---------------- scratch (no allocation allowed; 16B aligned) ----------------
__device__ __align__(16) float g_yz1[N_NODES * 256];   // [y1 = x@W1l | z1 = x@W1r]
__device__ __align__(16) float g_h1 [N_NODES * 128];   // relu hidden
__device__ __align__(16) float g_yz2[N_NODES * 64];    // [y2 = h1@W2l | z2 = h1@W2r]
__device__ __align__(16) float g_W1 [128 * 256];       // [W1l | W1r], K x 256
__device__ __align__(16) float g_W2 [128 * 64];        // [W2l | W2r], K x 64
__device__ __align__(16) int   g_src  [N_EDGES];       // normalized edge sources
__device__ __align__(16) int   g_dst  [N_EDGES];       // normalized edge dests
__device__ __align__(16) int   g_deg  [N_NODES];       // in-degree
__device__ __align__(16) int   g_start[N_NODES];       // CSR row starts (exclusive scan)
__device__ __align__(16) int   g_fill [N_NODES];       // fill cursors
__device__ __align__(16) int   g_csr  [N_EDGES];       // src per incoming edge, grouped by dst
__device__ int g_is64;                                  // edge_index dtype flag

// ---- packed f32x2 helpers (sm_103a) ----
#define PACK_BCAST(d, f)  asm("mov.b64 %0, {%1, %1};" : "=l"(d) : "r"(__float_as_uint(f)))
#define FMA2(acc, a, b)   asm("fma.rn.f32x2 %0, %1, %2, %0;" : "+l"(acc) : "l"(a), "l"(b))
#define UNPACK2(lo, hi, v) asm("mov.b64 {%0, %1}, %2;" : "=r"(lo), "=r"(hi) : "l"(v))

// ---------------- dtype detect: int64 vs int32 edge_index -------------------
__global__ void detect_kernel(const void* ei) {
    if (blockIdx.x | threadIdx.x) return;
    const long long* p = (const long long*)ei;
    int ok = 1;
    const int stride = N_EDGES / 64;
#pragma unroll 1
    for (int i = 0; i < 64; i++) {
        long long v = p[i * stride];
        if (v < 0 || v >= N_NODES) { ok = 0; break; }
    }
    g_is64 = ok;
}

// ---------------- setup: zero deg/fill + pack weights -----------------------
__global__ void setup_kernel(const float* __restrict__ W1l, const float* __restrict__ W1r,
                             const float* __restrict__ W2l, const float* __restrict__ W2r) {
    int tid = blockIdx.x * blockDim.x + threadIdx.x;
    if (tid < N_NODES) { g_deg[tid] = 0; g_fill[tid] = 0; }
    if (tid < 128 * 256) {
        int k = tid >> 8, n = tid & 255;
        g_W1[tid] = (n < 128) ? W1l[k * 128 + n] : W1r[k * 128 + (n - 128)];
    }
    if (tid < 128 * 64) {
        int k = tid >> 6, n = tid & 63;
        g_W2[tid] = (n < 32) ? W2l[k * 32 + n] : W2r[k * 32 + (n - 32)];
    }
}

// ---------------- normalize edges + count degrees (fused) -------------------
__global__ void convert_count_kernel(const void* ei) {
    int e = blockIdx.x * blockDim.x + threadIdx.x;
    if (e >= N_EDGES) return;
    int s, d;
    if (g_is64) {
        const long long* p = (const long long*)ei;
        s = (int)p[e]; d = (int)p[N_EDGES + e];
    } else {
        const int* p = (const int*)ei;
        s = p[e]; d = p[N_EDGES + e];
    }
    s = min(max(s, 0), N_NODES - 1);
    d = min(max(d, 0), N_NODES - 1);
    g_src[e] = s;
    g_dst[e] = d;
    atomicAdd(&g_deg[d], 1);
}

// ---------------- exclusive scan of g_deg -> g_start (1 block) ----------------
__global__ void __launch_bounds__(1024) scan_kernel() {
    __shared__ int wsum[32];
    __shared__ int carry_sh;
    int tid = threadIdx.x, lane = tid & 31, wid = tid >> 5;
    if (tid == 0) carry_sh = 0;
    __syncthreads();
    for (int base = 0; base < N_NODES; base += 1024) {
        int i = base + tid;
        int v = (i < N_NODES) ? g_deg[i] : 0;
        int inc = v;
#pragma unroll
        for (int o = 1; o < 32; o <<= 1) {
            int t = __shfl_up_sync(0xFFFFFFFFu, inc, o);
            if (lane >= o) inc += t;
        }
        if (lane == 31) wsum[wid] = inc;
        __syncthreads();
        if (wid == 0) {
            int s = wsum[lane];
#pragma unroll
            for (int o = 1; o < 32; o <<= 1) {
                int t = __shfl_up_sync(0xFFFFFFFFu, s, o);
                if (lane >= o) s += t;
            }
            wsum[lane] = s;
        }
        __syncthreads();
        int woff = wid ? wsum[wid - 1] : 0;
        if (i < N_NODES) g_start[i] = carry_sh + woff + inc - v;
        __syncthreads();
        if (tid == 1023) carry_sh += woff + inc;
        __syncthreads();
    }
}

// ---------------- CSR fill (int atomics) ----------------
__global__ void fill_kernel() {
    int e = blockIdx.x * blockDim.x + threadIdx.x;
    if (e >= N_EDGES) return;
    int dst = g_dst[e];
    int pos = g_start[dst] + atomicAdd(&g_fill[dst], 1);
    g_csr[pos] = g_src[e];
}

// ---------------- tiled SGEMM, K=128, packed f32x2 inner loop ----------------
// C[M x N] = A[M x 128] @ B[128 x N].  BM=128, BK=16, 256 threads, TM=8 (4 row-pairs).
template <int BN, int TN>
__global__ void __launch_bounds__(256)
sgemm_k128(const float* __restrict__ A, const float* __restrict__ B,
           float* __restrict__ C, int M, int N) {
    constexpr int BM = 128, BK = 16, TM = 8, TM2 = TM / 2;
    __shared__ float As[BK][BM];   // [k][m], row-pair contiguous in m
    __shared__ float Bs[BK][BN];

    const int tid = threadIdx.x;
    const int tx  = tid % (BN / TN);
    const int ty  = tid / (BN / TN);
    const int mBase = blockIdx.x * BM;
    const int nBase = blockIdx.y * BN;

    unsigned long long acc2[TM2][TN];   // packed (row 2m2, row 2m2+1)
#pragma unroll
    for (int m = 0; m < TM2; m++)
#pragma unroll
        for (int n = 0; n < TN; n++) acc2[m][n] = 0ULL;

    for (int k0 = 0; k0 < 128; k0 += BK) {
#pragma unroll
        for (int it = 0; it < (BM * BK / 4) / 256; it++) {
            int idx = tid + it * 256;
            int row = idx >> 2, c4 = idx & 3;
            float4 v = make_float4(0.f, 0.f, 0.f, 0.f);
            int gr = mBase + row;
            if (gr < M) v = *(const float4*)(A + (size_t)gr * 128 + k0 + c4 * 4);
            As[c4 * 4 + 0][row] = v.x;
            As[c4 * 4 + 1][row] = v.y;
            As[c4 * 4 + 2][row] = v.z;
            As[c4 * 4 + 3][row] = v.w;
        }
#pragma unroll
        for (int it = 0; it < (BK * BN / 4) / 256; it++) {
            int idx = tid + it * 256;
            int row = idx / (BN / 4), c4 = idx % (BN / 4);
            *(float4*)(&Bs[row][c4 * 4]) =
                *(const float4*)(B + (size_t)(k0 + row) * N + nBase + c4 * 4);
        }
        __syncthreads();

#pragma unroll
        for (int kk = 0; kk < BK; kk++) {
            unsigned long long a2[TM2], b2[TN];
#pragma unroll
            for (int m = 0; m < TM2; m++)
                a2[m] = *(const unsigned long long*)(&As[kk][ty * TM + m * 2]);
#pragma unroll
            for (int n = 0; n < TN; n++) {
                float bv = Bs[kk][tx * TN + n];
                PACK_BCAST(b2[n], bv);
            }
#pragma unroll
            for (int m = 0; m < TM2; m++)
#pragma unroll
                for (int n = 0; n < TN; n++) FMA2(acc2[m][n], a2[m], b2[n]);
        }
        __syncthreads();
    }

    // writeout: unpack row pairs
#pragma unroll
    for (int m = 0; m < TM2; m++) {
        int r0 = mBase + ty * TM + m * 2;
        float lo[TN], hi[TN];
#pragma unroll
        for (int n = 0; n < TN; n++) {
            unsigned int ul, uh;
            UNPACK2(ul, uh, acc2[m][n]);
            lo[n] = __uint_as_float(ul);
            hi[n] = __uint_as_float(uh);
        }
        if (r0 < M) {
#pragma unroll
            for (int n = 0; n < TN; n += 4)
                *(float4*)(C + (size_t)r0 * N + nBase + tx * TN + n) =
                    make_float4(lo[n], lo[n + 1], lo[n + 2], lo[n + 3]);
        }
        if (r0 + 1 < M) {
#pragma unroll
            for (int n = 0; n < TN; n += 4)
                *(float4*)(C + (size_t)(r0 + 1) * N + nBase + tx * TN + n) =
                    make_float4(hi[n], hi[n + 1], hi[n + 2], hi[n + 3]);
        }
    }
}

// ---------------- layer-1 gather + epilogue: h1 = relu(mean(y1[src]) + z1 + b1) ----
__global__ void gather1_kernel(const float* __restrict__ b1) {
    int node = (blockIdx.x * blockDim.x + threadIdx.x) >> 5;  // warp per node
    if (node >= N_NODES) return;
    int lane = threadIdx.x & 31;

    int start = g_start[node];
    int deg   = g_deg[node];

    float4 acc = make_float4(0.f, 0.f, 0.f, 0.f);
    for (int e0 = 0; e0 < deg; e0 += 32) {
        int m = min(32, deg - e0);
        int myidx = e0 + lane;
        int s = (myidx < deg) ? g_csr[start + myidx] : 0;
        for (int j = 0; j < m; j++) {
            int src = __shfl_sync(0xFFFFFFFFu, s, j);
            float4 v = ((const float4*)g_yz1)[(size_t)src * 64 + lane];  // y1 row
            acc.x += v.x; acc.y += v.y; acc.z += v.z; acc.w += v.w;
        }
    }
    float inv = (deg > 0) ? 1.0f / (float)deg : 0.0f;
    float4 z  = ((const float4*)g_yz1)[(size_t)node * 64 + 32 + lane];   // z1 row
    float4 bb = ((const float4*)b1)[lane];
    float4 r;
    r.x = fmaxf(fmaf(acc.x, inv, z.x + bb.x), 0.f);
    r.y = fmaxf(fmaf(acc.y, inv, z.y + bb.y), 0.f);
    r.z = fmaxf(fmaf(acc.z, inv, z.z + bb.z), 0.f);
    r.w = fmaxf(fmaf(acc.w, inv, z.w + bb.w), 0.f);
    ((float4*)g_h1)[(size_t)node * 32 + lane] = r;
}

// ---------------- layer-2 gather + log_softmax, fully fused ----------------
__global__ void gather2_kernel(const float* __restrict__ b2, float* __restrict__ out) {
    int node = (blockIdx.x * blockDim.x + threadIdx.x) >> 5;  // warp per node
    if (node >= N_NODES) return;
    int lane = threadIdx.x & 31;                               // = output channel

    int start = g_start[node];
    int deg   = g_deg[node];

    float acc = 0.f;
    for (int e0 = 0; e0 < deg; e0 += 32) {
        int m = min(32, deg - e0);
        int myidx = e0 + lane;
        int s = (myidx < deg) ? g_csr[start + myidx] : 0;
        for (int j = 0; j < m; j++) {
            int src = __shfl_sync(0xFFFFFFFFu, s, j);
            acc += g_yz2[(size_t)src * 64 + lane];             // y2 row, coalesced 128B
        }
    }
    float inv = (deg > 0) ? 1.0f / (float)deg : 0.0f;
    float v = fmaf(acc, inv, g_yz2[(size_t)node * 64 + 32 + lane] + b2[lane]);

    float mx = v;
#pragma unroll
    for (int o = 16; o > 0; o >>= 1) mx = fmaxf(mx, __shfl_xor_sync(0xFFFFFFFFu, mx, o));
    float ex = expf(v - mx);
    float s = ex;
#pragma unroll
    for (int o = 16; o > 0; o >>= 1) s += __shfl_xor_sync(0xFFFFFFFFu, s, o);
    out[(size_t)node * 32 + lane] = v - mx - logf(s);
}

// ---------------- launch ----------------
extern "C" void kernel_launch(void* const* d_in, const int* in_sizes, int n_in,
                              void* d_out, int out_size) {
    const float* x   = (const float*)d_in[0];
    const void*  ei  = d_in[1];
    const float* W1l = (const float*)d_in[2];
    const float* W1r = (const float*)d_in[3];
    const float* b1  = (const float*)d_in[4];
    const float* W2l = (const float*)d_in[5];
    const float* W2r = (const float*)d_in[6];
    const float* b2  = (const float*)d_in[7];
    float* out = (float*)d_out;

    float *p_yz1, *p_h1, *p_yz2, *p_W1, *p_W2;
    cudaGetSymbolAddress((void**)&p_yz1, g_yz1);
    cudaGetSymbolAddress((void**)&p_h1,  g_h1);
    cudaGetSymbolAddress((void**)&p_yz2, g_yz2);
    cudaGetSymbolAddress((void**)&p_W1,  g_W1);
    cudaGetSymbolAddress((void**)&p_W2,  g_W2);

    detect_kernel<<<1, 32>>>(ei);
    setup_kernel<<<(N_NODES + 255) / 256, 256>>>(W1l, W1r, W2l, W2r);
    convert_count_kernel<<<(N_EDGES + 255) / 256, 256>>>(ei);
    scan_kernel<<<1, 1024>>>();
    fill_kernel<<<(N_EDGES + 255) / 256, 256>>>();

    // yz1 = x @ [W1l | W1r]   (M=50000, K=128, N=256)
    {
        dim3 grid((N_NODES + 127) / 128, 2);
        sgemm_k128<128, 8><<<grid, 256>>>(x, p_W1, p_yz1, N_NODES, 256);
    }
    gather1_kernel<<<(N_NODES * 32 + 255) / 256, 256>>>(b1);

    // yz2 = h1 @ [W2l | W2r]  (M=50000, K=128, N=64)
    {
        dim3 grid((N_NODES + 127) / 128, 1);
        sgemm_k128<64, 4><<<grid, 256>>>(p_h1, p_W2, p_yz2, N_NODES, 64);
    }
    gather2_kernel<<<(N_NODES * 32 + 255) / 256, 256>>>(b2, out);
}

// round 7
// speedup vs baseline: 1.1894x; 1.1275x over previous
#include <cuda_runtime.h>
#include <cstdint>

#define N_NODES 50000
#define N_EDGES 800000
#define SCAN_BLK 1024
#define N_SCAN_BLOCKS ((N_NODES + SCAN_BLK - 1) / SCAN_BLK)   // 49

// ---------------- scratch (no allocation allowed; 16B aligned) ----------------
__device__ __align__(16) float g_yz1[N_NODES * 256];   // [y1 = x@W1l | z1 = x@W1r]
__device__ __align__(16) float g_h1 [N_NODES * 128];   // relu hidden
__device__ __align__(16) float g_yz2[N_NODES * 64];    // [y2 = h1@W2l | z2 = h1@W2r]
__device__ __align__(16) float g_W1 [128 * 256];       // [W1l | W1r], K x 256
__device__ __align__(16) float g_W2 [128 * 64];        // [W2l | W2r], K x 64
__device__ __align__(16) int   g_src  [N_EDGES];       // normalized edge sources
__device__ __align__(16) int   g_dst  [N_EDGES];       // normalized edge dests
__device__ __align__(16) int   g_deg  [N_NODES];       // in-degree
__device__ __align__(16) int   g_start[N_NODES];       // CSR row starts (exclusive scan)
__device__ __align__(16) int   g_fill [N_NODES];       // fill cursors
__device__ __align__(16) int   g_csr  [N_EDGES];       // src per incoming edge, grouped by dst
__device__ __align__(16) int   g_blksum[64];           // per-block totals (padded)
__device__ __align__(16) int   g_blkoff[64];           // exclusive scan of block totals
__device__ int g_is64;                                  // edge_index dtype flag

// ---- packed f32x2 helpers (sm_103a) ----
#define PACK_BCAST(d, f)  asm("mov.b64 %0, {%1, %1};" : "=l"(d) : "r"(__float_as_uint(f)))
#define FMA2(acc, a, b)   asm("fma.rn.f32x2 %0, %1, %2, %0;" : "+l"(acc) : "l"(a), "l"(b))
#define UNPACK2(lo, hi, v) asm("mov.b64 {%0, %1}, %2;" : "=r"(lo), "=r"(hi) : "l"(v))

// ---------------- dtype detect: int64 vs int32 edge_index -------------------
__global__ void detect_kernel(const void* ei) {
    if (blockIdx.x | threadIdx.x) return;
    const long long* p = (const long long*)ei;
    int ok = 1;
    const int stride = N_EDGES / 64;
#pragma unroll 1
    for (int i = 0; i < 64; i++) {
        long long v = p[i * stride];
        if (v < 0 || v >= N_NODES) { ok = 0; break; }
    }
    g_is64 = ok;
}

// ---------------- setup: zero deg/fill + pack weights -----------------------
__global__ void setup_kernel(const float* __restrict__ W1l, const float* __restrict__ W1r,
                             const float* __restrict__ W2l, const float* __restrict__ W2r) {
    int tid = blockIdx.x * blockDim.x + threadIdx.x;
    if (tid < N_NODES) { g_deg[tid] = 0; g_fill[tid] = 0; }
    if (tid < 128 * 256) {
        int k = tid >> 8, n = tid & 255;
        g_W1[tid] = (n < 128) ? W1l[k * 128 + n] : W1r[k * 128 + (n - 128)];
    }
    if (tid < 128 * 64) {
        int k = tid >> 6, n = tid & 63;
        g_W2[tid] = (n < 32) ? W2l[k * 32 + n] : W2r[k * 32 + (n - 32)];
    }
}

// ---------------- normalize edges + count degrees (fused) -------------------
__global__ void convert_count_kernel(const void* ei) {
    int e = blockIdx.x * blockDim.x + threadIdx.x;
    if (e >= N_EDGES) return;
    int s, d;
    if (g_is64) {
        const long long* p = (const long long*)ei;
        s = (int)p[e]; d = (int)p[N_EDGES + e];
    } else {
        const int* p = (const int*)ei;
        s = p[e]; d = p[N_EDGES + e];
    }
    s = min(max(s, 0), N_NODES - 1);
    d = min(max(d, 0), N_NODES - 1);
    g_src[e] = s;
    g_dst[e] = d;
    atomicAdd(&g_deg[d], 1);
}

// ---------------- parallel scan, phase A: per-block exclusive scan ----------
__global__ void __launch_bounds__(SCAN_BLK) scanA_kernel() {
    __shared__ int wsum[32];
    int tid = threadIdx.x, lane = tid & 31, wid = tid >> 5;
    int i = blockIdx.x * SCAN_BLK + tid;
    int v = (i < N_NODES) ? g_deg[i] : 0;
    int inc = v;
#pragma unroll
    for (int o = 1; o < 32; o <<= 1) {
        int t = __shfl_up_sync(0xFFFFFFFFu, inc, o);
        if (lane >= o) inc += t;
    }
    if (lane == 31) wsum[wid] = inc;
    __syncthreads();
    if (wid == 0) {
        int s = wsum[lane];
#pragma unroll
        for (int o = 1; o < 32; o <<= 1) {
            int t = __shfl_up_sync(0xFFFFFFFFu, s, o);
            if (lane >= o) s += t;
        }
        wsum[lane] = s;
    }
    __syncthreads();
    int woff = wid ? wsum[wid - 1] : 0;
    if (i < N_NODES) g_start[i] = woff + inc - v;   // block-local exclusive
    if (tid == SCAN_BLK - 1) g_blksum[blockIdx.x] = wsum[31];
}

// ---------------- phase B: scan 49 block totals (1 tiny block) ---------------
__global__ void scanB_kernel() {
    __shared__ int sh[64];
    int t = threadIdx.x;                   // 64 threads
    sh[t] = (t < N_SCAN_BLOCKS) ? g_blksum[t] : 0;
    __syncthreads();
#pragma unroll
    for (int o = 1; o < 64; o <<= 1) {
        int v = (t >= o) ? sh[t - o] : 0;
        __syncthreads();
        sh[t] += v;
        __syncthreads();
    }
    if (t < N_SCAN_BLOCKS) g_blkoff[t] = sh[t] - g_blksum[t];  // exclusive
}

// ---------------- phase C: add block offsets ----------------
__global__ void __launch_bounds__(SCAN_BLK) scanC_kernel() {
    int i = blockIdx.x * SCAN_BLK + threadIdx.x;
    if (i < N_NODES) g_start[i] += g_blkoff[blockIdx.x];
}

// ---------------- CSR fill (int atomics) ----------------
__global__ void fill_kernel() {
    int e = blockIdx.x * blockDim.x + threadIdx.x;
    if (e >= N_EDGES) return;
    int dst = g_dst[e];
    int pos = g_start[dst] + atomicAdd(&g_fill[dst], 1);
    g_csr[pos] = g_src[e];
}

// ---------------- tiled SGEMM, K=128, packed f32x2 inner loop ----------------
// C[M x N] = A[M x 128] @ B[128 x N].  BM=128, BK=16, 256 threads, TM=8 (4 row-pairs).
template <int BN, int TN>
__global__ void __launch_bounds__(256)
sgemm_k128(const float* __restrict__ A, const float* __restrict__ B,
           float* __restrict__ C, int M, int N) {
    constexpr int BM = 128, BK = 16, TM = 8, TM2 = TM / 2;
    __shared__ float As[BK][BM];   // [k][m], row-pair contiguous in m
    __shared__ float Bs[BK][BN];

    const int tid = threadIdx.x;
    const int tx  = tid % (BN / TN);
    const int ty  = tid / (BN / TN);
    const int mBase = blockIdx.x * BM;
    const int nBase = blockIdx.y * BN;

    unsigned long long acc2[TM2][TN];   // packed (row 2m2, row 2m2+1)
#pragma unroll
    for (int m = 0; m < TM2; m++)
#pragma unroll
        for (int n = 0; n < TN; n++) acc2[m][n] = 0ULL;

    for (int k0 = 0; k0 < 128; k0 += BK) {
#pragma unroll
        for (int it = 0; it < (BM * BK / 4) / 256; it++) {
            int idx = tid + it * 256;
            int row = idx >> 2, c4 = idx & 3;
            float4 v = make_float4(0.f, 0.f, 0.f, 0.f);
            int gr = mBase + row;
            if (gr < M) v = *(const float4*)(A + (size_t)gr * 128 + k0 + c4 * 4);
            As[c4 * 4 + 0][row] = v.x;
            As[c4 * 4 + 1][row] = v.y;
            As[c4 * 4 + 2][row] = v.z;
            As[c4 * 4 + 3][row] = v.w;
        }
#pragma unroll
        for (int it = 0; it < (BK * BN / 4) / 256; it++) {
            int idx = tid + it * 256;
            int row = idx / (BN / 4), c4 = idx % (BN / 4);
            *(float4*)(&Bs[row][c4 * 4]) =
                *(const float4*)(B + (size_t)(k0 + row) * N + nBase + c4 * 4);
        }
        __syncthreads();

#pragma unroll
        for (int kk = 0; kk < BK; kk++) {
            unsigned long long a2[TM2], b2[TN];
#pragma unroll
            for (int m = 0; m < TM2; m++)
                a2[m] = *(const unsigned long long*)(&As[kk][ty * TM + m * 2]);
#pragma unroll
            for (int n = 0; n < TN; n++) {
                float bv = Bs[kk][tx * TN + n];
                PACK_BCAST(b2[n], bv);
            }
#pragma unroll
            for (int m = 0; m < TM2; m++)
#pragma unroll
                for (int n = 0; n < TN; n++) FMA2(acc2[m][n], a2[m], b2[n]);
        }
        __syncthreads();
    }

    // writeout: unpack row pairs
#pragma unroll
    for (int m = 0; m < TM2; m++) {
        int r0 = mBase + ty * TM + m * 2;
        float lo[TN], hi[TN];
#pragma unroll
        for (int n = 0; n < TN; n++) {
            unsigned int ul, uh;
            UNPACK2(ul, uh, acc2[m][n]);
            lo[n] = __uint_as_float(ul);
            hi[n] = __uint_as_float(uh);
        }
        if (r0 < M) {
#pragma unroll
            for (int n = 0; n < TN; n += 4)
                *(float4*)(C + (size_t)r0 * N + nBase + tx * TN + n) =
                    make_float4(lo[n], lo[n + 1], lo[n + 2], lo[n + 3]);
        }
        if (r0 + 1 < M) {
#pragma unroll
            for (int n = 0; n < TN; n += 4)
                *(float4*)(C + (size_t)(r0 + 1) * N + nBase + tx * TN + n) =
                    make_float4(hi[n], hi[n + 1], hi[n + 2], hi[n + 3]);
        }
    }
}

// ---------------- layer-1 gather + epilogue: h1 = relu(mean(y1[src]) + z1 + b1) ----
__global__ void gather1_kernel(const float* __restrict__ b1) {
    int node = (blockIdx.x * blockDim.x + threadIdx.x) >> 5;  // warp per node
    if (node >= N_NODES) return;
    int lane = threadIdx.x & 31;

    int start = g_start[node];
    int deg   = g_deg[node];

    float4 acc = make_float4(0.f, 0.f, 0.f, 0.f);
    for (int e0 = 0; e0 < deg; e0 += 32) {
        int m = min(32, deg - e0);
        int myidx = e0 + lane;
        int s = (myidx < deg) ? g_csr[start + myidx] : 0;
        for (int j = 0; j < m; j++) {
            int src = __shfl_sync(0xFFFFFFFFu, s, j);
            float4 v = ((const float4*)g_yz1)[(size_t)src * 64 + lane];  // y1 row
            acc.x += v.x; acc.y += v.y; acc.z += v.z; acc.w += v.w;
        }
    }
    float inv = (deg > 0) ? 1.0f / (float)deg : 0.0f;
    float4 z  = ((const float4*)g_yz1)[(size_t)node * 64 + 32 + lane];   // z1 row
    float4 bb = ((const float4*)b1)[lane];
    float4 r;
    r.x = fmaxf(fmaf(acc.x, inv, z.x + bb.x), 0.f);
    r.y = fmaxf(fmaf(acc.y, inv, z.y + bb.y), 0.f);
    r.z = fmaxf(fmaf(acc.z, inv, z.z + bb.z), 0.f);
    r.w = fmaxf(fmaf(acc.w, inv, z.w + bb.w), 0.f);
    ((float4*)g_h1)[(size_t)node * 32 + lane] = r;
}

// ---------------- layer-2 gather + log_softmax, fully fused ----------------
__global__ void gather2_kernel(const float* __restrict__ b2, float* __restrict__ out) {
    int node = (blockIdx.x * blockDim.x + threadIdx.x) >> 5;  // warp per node
    if (node >= N_NODES) return;
    int lane = threadIdx.x & 31;                               // = output channel

    int start = g_start[node];
    int deg   = g_deg[node];

    float acc = 0.f;
    for (int e0 = 0; e0 < deg; e0 += 32) {
        int m = min(32, deg - e0);
        int myidx = e0 + lane;
        int s = (myidx < deg) ? g_csr[start + myidx] : 0;
        for (int j = 0; j < m; j++) {
            int src = __shfl_sync(0xFFFFFFFFu, s, j);
            acc += g_yz2[(size_t)src * 64 + lane];             // y2 row, coalesced 128B
        }
    }
    float inv = (deg > 0) ? 1.0f / (float)deg : 0.0f;
    float v = fmaf(acc, inv, g_yz2[(size_t)node * 64 + 32 + lane] + b2[lane]);

    float mx = v;
#pragma unroll
    for (int o = 16; o > 0; o >>= 1) mx = fmaxf(mx, __shfl_xor_sync(0xFFFFFFFFu, mx, o));
    float ex = expf(v - mx);
    float s = ex;
#pragma unroll
    for (int o = 16; o > 0; o >>= 1) s += __shfl_xor_sync(0xFFFFFFFFu, s, o);
    out[(size_t)node * 32 + lane] = v - mx - logf(s);
}

// ---------------- launch ----------------
extern "C" void kernel_launch(void* const* d_in, const int* in_sizes, int n_in,
                              void* d_out, int out_size) {
    const float* x   = (const float*)d_in[0];
    const void*  ei  = d_in[1];
    const float* W1l = (const float*)d_in[2];
    const float* W1r = (const float*)d_in[3];
    const float* b1  = (const float*)d_in[4];
    const float* W2l = (const float*)d_in[5];
    const float* W2r = (const float*)d_in[6];
    const float* b2  = (const float*)d_in[7];
    float* out = (float*)d_out;

    float *p_yz1, *p_h1, *p_yz2, *p_W1, *p_W2;
    cudaGetSymbolAddress((void**)&p_yz1, g_yz1);
    cudaGetSymbolAddress((void**)&p_h1,  g_h1);
    cudaGetSymbolAddress((void**)&p_yz2, g_yz2);
    cudaGetSymbolAddress((void**)&p_W1,  g_W1);
    cudaGetSymbolAddress((void**)&p_W2,  g_W2);

    detect_kernel<<<1, 32>>>(ei);
    setup_kernel<<<(N_NODES + 255) / 256, 256>>>(W1l, W1r, W2l, W2r);
    convert_count_kernel<<<(N_EDGES + 255) / 256, 256>>>(ei);
    scanA_kernel<<<N_SCAN_BLOCKS, SCAN_BLK>>>();
    scanB_kernel<<<1, 64>>>();
    scanC_kernel<<<N_SCAN_BLOCKS, SCAN_BLK>>>();
    fill_kernel<<<(N_EDGES + 255) / 256, 256>>>();

    // yz1 = x @ [W1l | W1r]   (M=50000, K=128, N=256)
    {
        dim3 grid((N_NODES + 127) / 128, 2);
        sgemm_k128<128, 8><<<grid, 256>>>(x, p_W1, p_yz1, N_NODES, 256);
    }
    gather1_kernel<<<(N_NODES * 32 + 255) / 256, 256>>>(b1);

    // yz2 = h1 @ [W2l | W2r]  (M=50000, K=128, N=64)
    {
        dim3 grid((N_NODES + 127) / 128, 1);
        sgemm_k128<64, 4><<<grid, 256>>>(p_h1, p_W2, p_yz2, N_NODES, 64);
    }
    gather2_kernel<<<(N_NODES * 32 + 255) / 256, 256>>>(b2, out);
}

// round 8
// speedup vs baseline: 1.2627x; 1.0616x over previous
#include <cuda_runtime.h>
#include <cstdint>

#define N_NODES 50000
#define N_EDGES 800000
#define SCAN_BLK 1024
#define N_SCAN_BLOCKS ((N_NODES + SCAN_BLK - 1) / SCAN_BLK)   // 49

// ---------------- scratch (no allocation allowed; 16B aligned) ----------------
__device__ __align__(16) float g_yz1[N_NODES * 256];   // [y1 = x@W1l | z1 = x@W1r]
__device__ __align__(16) float g_h1 [N_NODES * 128];   // relu hidden
__device__ __align__(16) float g_yz2[N_NODES * 64];    // [y2 = h1@W2l | z2 = h1@W2r]
__device__ __align__(16) float g_W1 [128 * 256];       // [W1l | W1r], K x 256
__device__ __align__(16) float g_W2 [128 * 64];        // [W2l | W2r], K x 64
__device__ __align__(16) int   g_src  [N_EDGES];       // normalized edge sources
__device__ __align__(16) int   g_dst  [N_EDGES];       // normalized edge dests
__device__ __align__(16) int   g_deg  [N_NODES];       // in-degree
__device__ __align__(16) int   g_start[N_NODES];       // CSR row starts (exclusive scan)
__device__ __align__(16) int   g_fill [N_NODES];       // fill cursors
__device__ __align__(16) int   g_csr  [N_EDGES];       // src per incoming edge, grouped by dst
__device__ __align__(16) int   g_blksum[64];           // per-block totals (padded)
__device__ __align__(16) int   g_blkoff[64];           // exclusive scan of block totals
__device__ int g_is64;                                  // edge_index dtype flag

// ---- packed f32x2 helpers (sm_103a) ----
#define PACK_BCAST(d, f)  asm("mov.b64 %0, {%1, %1};" : "=l"(d) : "r"(__float_as_uint(f)))
#define FMA2(acc, a, b)   asm("fma.rn.f32x2 %0, %1, %2, %0;" : "+l"(acc) : "l"(a), "l"(b))
#define UNPACK2(lo, hi, v) asm("mov.b64 {%0, %1}, %2;" : "=r"(lo), "=r"(hi) : "l"(v))

// ---------------- dtype detect: int64 vs int32 edge_index -------------------
__global__ void detect_kernel(const void* ei) {
    if (blockIdx.x | threadIdx.x) return;
    const long long* p = (const long long*)ei;
    int ok = 1;
    const int stride = N_EDGES / 64;
#pragma unroll 1
    for (int i = 0; i < 64; i++) {
        long long v = p[i * stride];
        if (v < 0 || v >= N_NODES) { ok = 0; break; }
    }
    g_is64 = ok;
}

// ---------------- setup: zero deg/fill + pack weights -----------------------
__global__ void setup_kernel(const float* __restrict__ W1l, const float* __restrict__ W1r,
                             const float* __restrict__ W2l, const float* __restrict__ W2r) {
    int tid = blockIdx.x * blockDim.x + threadIdx.x;
    if (tid < N_NODES) { g_deg[tid] = 0; g_fill[tid] = 0; }
    if (tid < 128 * 256) {
        int k = tid >> 8, n = tid & 255;
        g_W1[tid] = (n < 128) ? W1l[k * 128 + n] : W1r[k * 128 + (n - 128)];
    }
    if (tid < 128 * 64) {
        int k = tid >> 6, n = tid & 63;
        g_W2[tid] = (n < 32) ? W2l[k * 32 + n] : W2r[k * 32 + (n - 32)];
    }
}

// ---------------- normalize edges + count degrees (fused) -------------------
__global__ void convert_count_kernel(const void* ei) {
    int e = blockIdx.x * blockDim.x + threadIdx.x;
    if (e >= N_EDGES) return;
    int s, d;
    if (g_is64) {
        const long long* p = (const long long*)ei;
        s = (int)p[e]; d = (int)p[N_EDGES + e];
    } else {
        const int* p = (const int*)ei;
        s = p[e]; d = p[N_EDGES + e];
    }
    s = min(max(s, 0), N_NODES - 1);
    d = min(max(d, 0), N_NODES - 1);
    g_src[e] = s;
    g_dst[e] = d;
    atomicAdd(&g_deg[d], 1);
}

// ---------------- parallel scan, phase A: per-block exclusive scan ----------
__global__ void __launch_bounds__(SCAN_BLK) scanA_kernel() {
    __shared__ int wsum[32];
    int tid = threadIdx.x, lane = tid & 31, wid = tid >> 5;
    int i = blockIdx.x * SCAN_BLK + tid;
    int v = (i < N_NODES) ? g_deg[i] : 0;
    int inc = v;
#pragma unroll
    for (int o = 1; o < 32; o <<= 1) {
        int t = __shfl_up_sync(0xFFFFFFFFu, inc, o);
        if (lane >= o) inc += t;
    }
    if (lane == 31) wsum[wid] = inc;
    __syncthreads();
    if (wid == 0) {
        int s = wsum[lane];
#pragma unroll
        for (int o = 1; o < 32; o <<= 1) {
            int t = __shfl_up_sync(0xFFFFFFFFu, s, o);
            if (lane >= o) s += t;
        }
        wsum[lane] = s;
    }
    __syncthreads();
    int woff = wid ? wsum[wid - 1] : 0;
    if (i < N_NODES) g_start[i] = woff + inc - v;   // block-local exclusive
    if (tid == SCAN_BLK - 1) g_blksum[blockIdx.x] = wsum[31];
}

// ---------------- phase B: scan 49 block totals (1 tiny block) ---------------
__global__ void scanB_kernel() {
    __shared__ int sh[64];
    int t = threadIdx.x;                   // 64 threads
    sh[t] = (t < N_SCAN_BLOCKS) ? g_blksum[t] : 0;
    __syncthreads();
#pragma unroll
    for (int o = 1; o < 64; o <<= 1) {
        int v = (t >= o) ? sh[t - o] : 0;
        __syncthreads();
        sh[t] += v;
        __syncthreads();
    }
    if (t < N_SCAN_BLOCKS) g_blkoff[t] = sh[t] - g_blksum[t];  // exclusive
}

// ---------------- phase C: add block offsets ----------------
__global__ void __launch_bounds__(SCAN_BLK) scanC_kernel() {
    int i = blockIdx.x * SCAN_BLK + threadIdx.x;
    if (i < N_NODES) g_start[i] += g_blkoff[blockIdx.x];
}

// ---------------- CSR fill (int atomics) ----------------
__global__ void fill_kernel() {
    int e = blockIdx.x * blockDim.x + threadIdx.x;
    if (e >= N_EDGES) return;
    int dst = g_dst[e];
    int pos = g_start[dst] + atomicAdd(&g_fill[dst], 1);
    g_csr[pos] = g_src[e];
}

// ---------------- tiled SGEMM, K=128, packed f32x2 inner loop ----------------
// C[M x N] = A[M x 128] @ B[128 x N].  BM=128, BK=16, 256 threads, TM=8 (4 row-pairs).
template <int BN, int TN>
__global__ void __launch_bounds__(256)
sgemm_k128(const float* __restrict__ A, const float* __restrict__ B,
           float* __restrict__ C, int M, int N) {
    constexpr int BM = 128, BK = 16, TM = 8, TM2 = TM / 2;
    __shared__ float As[BK][BM];   // [k][m], row-pair contiguous in m
    __shared__ float Bs[BK][BN];

    const int tid = threadIdx.x;
    const int tx  = tid % (BN / TN);
    const int ty  = tid / (BN / TN);
    const int mBase = blockIdx.x * BM;
    const int nBase = blockIdx.y * BN;

    unsigned long long acc2[TM2][TN];   // packed (row 2m2, row 2m2+1)
#pragma unroll
    for (int m = 0; m < TM2; m++)
#pragma unroll
        for (int n = 0; n < TN; n++) acc2[m][n] = 0ULL;

    for (int k0 = 0; k0 < 128; k0 += BK) {
#pragma unroll
        for (int it = 0; it < (BM * BK / 4) / 256; it++) {
            int idx = tid + it * 256;
            int row = idx >> 2, c4 = idx & 3;
            float4 v = make_float4(0.f, 0.f, 0.f, 0.f);
            int gr = mBase + row;
            if (gr < M) v = *(const float4*)(A + (size_t)gr * 128 + k0 + c4 * 4);
            As[c4 * 4 + 0][row] = v.x;
            As[c4 * 4 + 1][row] = v.y;
            As[c4 * 4 + 2][row] = v.z;
            As[c4 * 4 + 3][row] = v.w;
        }
#pragma unroll
        for (int it = 0; it < (BK * BN / 4) / 256; it++) {
            int idx = tid + it * 256;
            int row = idx / (BN / 4), c4 = idx % (BN / 4);
            *(float4*)(&Bs[row][c4 * 4]) =
                *(const float4*)(B + (size_t)(k0 + row) * N + nBase + c4 * 4);
        }
        __syncthreads();

#pragma unroll
        for (int kk = 0; kk < BK; kk++) {
            unsigned long long a2[TM2], b2[TN];
#pragma unroll
            for (int m = 0; m < TM2; m++)
                a2[m] = *(const unsigned long long*)(&As[kk][ty * TM + m * 2]);
#pragma unroll
            for (int n = 0; n < TN; n++) {
                float bv = Bs[kk][tx * TN + n];
                PACK_BCAST(b2[n], bv);
            }
#pragma unroll
            for (int m = 0; m < TM2; m++)
#pragma unroll
                for (int n = 0; n < TN; n++) FMA2(acc2[m][n], a2[m], b2[n]);
        }
        __syncthreads();
    }

    // writeout: unpack row pairs
#pragma unroll
    for (int m = 0; m < TM2; m++) {
        int r0 = mBase + ty * TM + m * 2;
        float lo[TN], hi[TN];
#pragma unroll
        for (int n = 0; n < TN; n++) {
            unsigned int ul, uh;
            UNPACK2(ul, uh, acc2[m][n]);
            lo[n] = __uint_as_float(ul);
            hi[n] = __uint_as_float(uh);
        }
        if (r0 < M) {
#pragma unroll
            for (int n = 0; n < TN; n += 4)
                *(float4*)(C + (size_t)r0 * N + nBase + tx * TN + n) =
                    make_float4(lo[n], lo[n + 1], lo[n + 2], lo[n + 3]);
        }
        if (r0 + 1 < M) {
#pragma unroll
            for (int n = 0; n < TN; n += 4)
                *(float4*)(C + (size_t)(r0 + 1) * N + nBase + tx * TN + n) =
                    make_float4(hi[n], hi[n + 1], hi[n + 2], hi[n + 3]);
        }
    }
}

// ---------------- layer-1 gather + epilogue: h1 = relu(mean(y1[src]) + z1 + b1) ----
__global__ void gather1_kernel(const float* __restrict__ b1) {
    int node = (blockIdx.x * blockDim.x + threadIdx.x) >> 5;  // warp per node
    if (node >= N_NODES) return;
    int lane = threadIdx.x & 31;

    int start = g_start[node];
    int deg   = g_deg[node];

    float4 acc = make_float4(0.f, 0.f, 0.f, 0.f);
    for (int e0 = 0; e0 < deg; e0 += 32) {
        int m = min(32, deg - e0);
        int myidx = e0 + lane;
        int s = (myidx < deg) ? g_csr[start + myidx] : 0;
        for (int j = 0; j < m; j++) {
            int src = __shfl_sync(0xFFFFFFFFu, s, j);
            float4 v = ((const float4*)g_yz1)[(size_t)src * 64 + lane];  // y1 row
            acc.x += v.x; acc.y += v.y; acc.z += v.z; acc.w += v.w;
        }
    }
    float inv = (deg > 0) ? 1.0f / (float)deg : 0.0f;
    float4 z  = ((const float4*)g_yz1)[(size_t)node * 64 + 32 + lane];   // z1 row
    float4 bb = ((const float4*)b1)[lane];
    float4 r;
    r.x = fmaxf(fmaf(acc.x, inv, z.x + bb.x), 0.f);
    r.y = fmaxf(fmaf(acc.y, inv, z.y + bb.y), 0.f);
    r.z = fmaxf(fmaf(acc.z, inv, z.z + bb.z), 0.f);
    r.w = fmaxf(fmaf(acc.w, inv, z.w + bb.w), 0.f);
    ((float4*)g_h1)[(size_t)node * 32 + lane] = r;
}

// ---------------- layer-2 gather + log_softmax, fully fused ----------------
__global__ void gather2_kernel(const float* __restrict__ b2, float* __restrict__ out) {
    int node = (blockIdx.x * blockDim.x + threadIdx.x) >> 5;  // warp per node
    if (node >= N_NODES) return;
    int lane = threadIdx.x & 31;                               // = output channel

    int start = g_start[node];
    int deg   = g_deg[node];

    float acc = 0.f;
    for (int e0 = 0; e0 < deg; e0 += 32) {
        int m = min(32, deg - e0);
        int myidx = e0 + lane;
        int s = (myidx < deg) ? g_csr[start + myidx] : 0;
        for (int j = 0; j < m; j++) {
            int src = __shfl_sync(0xFFFFFFFFu, s, j);
            acc += g_yz2[(size_t)src * 64 + lane];             // y2 row, coalesced 128B
        }
    }
    float inv = (deg > 0) ? 1.0f / (float)deg : 0.0f;
    float v = fmaf(acc, inv, g_yz2[(size_t)node * 64 + 32 + lane] + b2[lane]);

    float mx = v;
#pragma unroll
    for (int o = 16; o > 0; o >>= 1) mx = fmaxf(mx, __shfl_xor_sync(0xFFFFFFFFu, mx, o));
    float ex = expf(v - mx);
    float s = ex;
#pragma unroll
    for (int o = 16; o > 0; o >>= 1) s += __shfl_xor_sync(0xFFFFFFFFu, s, o);
    out[(size_t)node * 32 + lane] = v - mx - logf(s);
}

// ---------------- launch ----------------
extern "C" void kernel_launch(void* const* d_in, const int* in_sizes, int n_in,
                              void* d_out, int out_size) {
    const float* x   = (const float*)d_in[0];
    const void*  ei  = d_in[1];
    const float* W1l = (const float*)d_in[2];
    const float* W1r = (const float*)d_in[3];
    const float* b1  = (const float*)d_in[4];
    const float* W2l = (const float*)d_in[5];
    const float* W2r = (const float*)d_in[6];
    const float* b2  = (const float*)d_in[7];
    float* out = (float*)d_out;

    float *p_yz1, *p_h1, *p_yz2, *p_W1, *p_W2;
    cudaGetSymbolAddress((void**)&p_yz1, g_yz1);
    cudaGetSymbolAddress((void**)&p_h1,  g_h1);
    cudaGetSymbolAddress((void**)&p_yz2, g_yz2);
    cudaGetSymbolAddress((void**)&p_W1,  g_W1);
    cudaGetSymbolAddress((void**)&p_W2,  g_W2);

    // side stream + fork/join events, created once on first (non-captured)
    // correctness call; per-call work is identical and deterministic.
    static cudaStream_t s2 = nullptr;
    static cudaEvent_t evFork = nullptr, evJoin = nullptr;
    if (!s2) {
        cudaStreamCreateWithFlags(&s2, cudaStreamNonBlocking);
        cudaEventCreateWithFlags(&evFork, cudaEventDisableTiming);
        cudaEventCreateWithFlags(&evJoin, cudaEventDisableTiming);
    }

    detect_kernel<<<1, 32>>>(ei);
    setup_kernel<<<(N_NODES + 255) / 256, 256>>>(W1l, W1r, W2l, W2r);

    // fork: CSR build on s2, GEMM1 on main stream (independent work)
    cudaEventRecord(evFork, 0);
    cudaStreamWaitEvent(s2, evFork, 0);

    convert_count_kernel<<<(N_EDGES + 255) / 256, 256, 0, s2>>>(ei);
    scanA_kernel<<<N_SCAN_BLOCKS, SCAN_BLK, 0, s2>>>();
    scanB_kernel<<<1, 64, 0, s2>>>();
    scanC_kernel<<<N_SCAN_BLOCKS, SCAN_BLK, 0, s2>>>();
    fill_kernel<<<(N_EDGES + 255) / 256, 256, 0, s2>>>();

    // yz1 = x @ [W1l | W1r]   (M=50000, K=128, N=256) — main stream
    {
        dim3 grid((N_NODES + 127) / 128, 2);
        sgemm_k128<128, 8><<<grid, 256>>>(x, p_W1, p_yz1, N_NODES, 256);
    }

    // join: gather1 needs CSR + yz1
    cudaEventRecord(evJoin, s2);
    cudaStreamWaitEvent(0, evJoin, 0);

    gather1_kernel<<<(N_NODES * 32 + 255) / 256, 256>>>(b1);

    // yz2 = h1 @ [W2l | W2r]  (M=50000, K=128, N=64)
    {
        dim3 grid((N_NODES + 127) / 128, 1);
        sgemm_k128<64, 4><<<grid, 256>>>(p_h1, p_W2, p_yz2, N_NODES, 64);
    }
    gather2_kernel<<<(N_NODES * 32 + 255) / 256, 256>>>(b2, out);
}

// round 9
// speedup vs baseline: 1.2805x; 1.0141x over previous
#include <cuda_runtime.h>
#include <cstdint>

#define N_NODES 50000
#define N_EDGES 800000
#define SCAN_BLK 1024
#define N_SCAN_BLOCKS ((N_NODES + SCAN_BLK - 1) / SCAN_BLK)   // 49

// ---------------- scratch (no allocation allowed; 16B aligned) ----------------
__device__ __align__(16) float g_y1 [N_NODES * 128];   // x @ W1l
__device__ __align__(16) float g_z1 [N_NODES * 128];   // x @ W1r
__device__ __align__(16) float g_h1 [N_NODES * 128];   // neighbor sum -> relu hidden (in-place)
__device__ __align__(16) float g_yz2[N_NODES * 64];    // [y2 = h1@W2l | z2 = h1@W2r]
__device__ __align__(16) float g_W1a[128 * 128];       // W1l, K x 128
__device__ __align__(16) float g_W1b[128 * 128];       // W1r, K x 128
__device__ __align__(16) float g_W2 [128 * 64];        // [W2l | W2r], K x 64
__device__ __align__(16) int   g_src  [N_EDGES];
__device__ __align__(16) int   g_dst  [N_EDGES];
__device__ __align__(16) int   g_deg  [N_NODES];
__device__ __align__(16) int   g_start[N_NODES];
__device__ __align__(16) int   g_fill [N_NODES];
__device__ __align__(16) int   g_csr  [N_EDGES];
__device__ __align__(16) int   g_blksum[64];
__device__ __align__(16) int   g_blkoff[64];
__device__ int g_is64;

// ---- packed f32x2 helpers (sm_103a) ----
#define PACK_BCAST(d, f)  asm("mov.b64 %0, {%1, %1};" : "=l"(d) : "r"(__float_as_uint(f)))
#define FMA2(acc, a, b)   asm("fma.rn.f32x2 %0, %1, %2, %0;" : "+l"(acc) : "l"(a), "l"(b))
#define UNPACK2(lo, hi, v) asm("mov.b64 {%0, %1}, %2;" : "=r"(lo), "=r"(hi) : "l"(v))

// ---------------- dtype detect: int64 vs int32 edge_index -------------------
__global__ void detect_kernel(const void* ei) {
    if (blockIdx.x | threadIdx.x) return;
    const long long* p = (const long long*)ei;
    int ok = 1;
    const int stride = N_EDGES / 64;
#pragma unroll 1
    for (int i = 0; i < 64; i++) {
        long long v = p[i * stride];
        if (v < 0 || v >= N_NODES) { ok = 0; break; }
    }
    g_is64 = ok;
}

// ---------------- setup: zero deg/fill + pack weights -----------------------
__global__ void setup_kernel(const float* __restrict__ W1l, const float* __restrict__ W1r,
                             const float* __restrict__ W2l, const float* __restrict__ W2r) {
    int tid = blockIdx.x * blockDim.x + threadIdx.x;
    if (tid < N_NODES) { g_deg[tid] = 0; g_fill[tid] = 0; }
    if (tid < 128 * 128) {
        g_W1a[tid] = W1l[tid];
        g_W1b[tid] = W1r[tid];
    }
    if (tid < 128 * 64) {
        int k = tid >> 6, n = tid & 63;
        g_W2[tid] = (n < 32) ? W2l[k * 32 + n] : W2r[k * 32 + (n - 32)];
    }
}

// ---------------- normalize edges + count degrees (fused) -------------------
__global__ void convert_count_kernel(const void* ei) {
    int e = blockIdx.x * blockDim.x + threadIdx.x;
    if (e >= N_EDGES) return;
    int s, d;
    if (g_is64) {
        const long long* p = (const long long*)ei;
        s = (int)p[e]; d = (int)p[N_EDGES + e];
    } else {
        const int* p = (const int*)ei;
        s = p[e]; d = p[N_EDGES + e];
    }
    s = min(max(s, 0), N_NODES - 1);
    d = min(max(d, 0), N_NODES - 1);
    g_src[e] = s;
    g_dst[e] = d;
    atomicAdd(&g_deg[d], 1);
}

// ---------------- parallel scan ----------------
__global__ void __launch_bounds__(SCAN_BLK) scanA_kernel() {
    __shared__ int wsum[32];
    int tid = threadIdx.x, lane = tid & 31, wid = tid >> 5;
    int i = blockIdx.x * SCAN_BLK + tid;
    int v = (i < N_NODES) ? g_deg[i] : 0;
    int inc = v;
#pragma unroll
    for (int o = 1; o < 32; o <<= 1) {
        int t = __shfl_up_sync(0xFFFFFFFFu, inc, o);
        if (lane >= o) inc += t;
    }
    if (lane == 31) wsum[wid] = inc;
    __syncthreads();
    if (wid == 0) {
        int s = wsum[lane];
#pragma unroll
        for (int o = 1; o < 32; o <<= 1) {
            int t = __shfl_up_sync(0xFFFFFFFFu, s, o);
            if (lane >= o) s += t;
        }
        wsum[lane] = s;
    }
    __syncthreads();
    int woff = wid ? wsum[wid - 1] : 0;
    if (i < N_NODES) g_start[i] = woff + inc - v;
    if (tid == SCAN_BLK - 1) g_blksum[blockIdx.x] = wsum[31];
}

__global__ void scanB_kernel() {
    __shared__ int sh[64];
    int t = threadIdx.x;
    sh[t] = (t < N_SCAN_BLOCKS) ? g_blksum[t] : 0;
    __syncthreads();
#pragma unroll
    for (int o = 1; o < 64; o <<= 1) {
        int v = (t >= o) ? sh[t - o] : 0;
        __syncthreads();
        sh[t] += v;
        __syncthreads();
    }
    if (t < N_SCAN_BLOCKS) g_blkoff[t] = sh[t] - g_blksum[t];
}

__global__ void __launch_bounds__(SCAN_BLK) scanC_kernel() {
    int i = blockIdx.x * SCAN_BLK + threadIdx.x;
    if (i < N_NODES) g_start[i] += g_blkoff[blockIdx.x];
}

// ---------------- CSR fill ----------------
__global__ void fill_kernel() {
    int e = blockIdx.x * blockDim.x + threadIdx.x;
    if (e >= N_EDGES) return;
    int dst = g_dst[e];
    int pos = g_start[dst] + atomicAdd(&g_fill[dst], 1);
    g_csr[pos] = g_src[e];
}

// ---------------- tiled SGEMM, K=128, packed f32x2 inner loop ----------------
template <int BN, int TN>
__global__ void __launch_bounds__(256)
sgemm_k128(const float* __restrict__ A, const float* __restrict__ B,
           float* __restrict__ C, int M, int N) {
    constexpr int BM = 128, BK = 16, TM = 8, TM2 = TM / 2;
    __shared__ float As[BK][BM];
    __shared__ float Bs[BK][BN];

    const int tid = threadIdx.x;
    const int tx  = tid % (BN / TN);
    const int ty  = tid / (BN / TN);
    const int mBase = blockIdx.x * BM;
    const int nBase = blockIdx.y * BN;

    unsigned long long acc2[TM2][TN];
#pragma unroll
    for (int m = 0; m < TM2; m++)
#pragma unroll
        for (int n = 0; n < TN; n++) acc2[m][n] = 0ULL;

    for (int k0 = 0; k0 < 128; k0 += BK) {
#pragma unroll
        for (int it = 0; it < (BM * BK / 4) / 256; it++) {
            int idx = tid + it * 256;
            int row = idx >> 2, c4 = idx & 3;
            float4 v = make_float4(0.f, 0.f, 0.f, 0.f);
            int gr = mBase + row;
            if (gr < M) v = *(const float4*)(A + (size_t)gr * 128 + k0 + c4 * 4);
            As[c4 * 4 + 0][row] = v.x;
            As[c4 * 4 + 1][row] = v.y;
            As[c4 * 4 + 2][row] = v.z;
            As[c4 * 4 + 3][row] = v.w;
        }
#pragma unroll
        for (int it = 0; it < (BK * BN / 4) / 256; it++) {
            int idx = tid + it * 256;
            int row = idx / (BN / 4), c4 = idx % (BN / 4);
            *(float4*)(&Bs[row][c4 * 4]) =
                *(const float4*)(B + (size_t)(k0 + row) * N + nBase + c4 * 4);
        }
        __syncthreads();

#pragma unroll
        for (int kk = 0; kk < BK; kk++) {
            unsigned long long a2[TM2], b2[TN];
#pragma unroll
            for (int m = 0; m < TM2; m++)
                a2[m] = *(const unsigned long long*)(&As[kk][ty * TM + m * 2]);
#pragma unroll
            for (int n = 0; n < TN; n++) {
                float bv = Bs[kk][tx * TN + n];
                PACK_BCAST(b2[n], bv);
            }
#pragma unroll
            for (int m = 0; m < TM2; m++)
#pragma unroll
                for (int n = 0; n < TN; n++) FMA2(acc2[m][n], a2[m], b2[n]);
        }
        __syncthreads();
    }

#pragma unroll
    for (int m = 0; m < TM2; m++) {
        int r0 = mBase + ty * TM + m * 2;
        float lo[TN], hi[TN];
#pragma unroll
        for (int n = 0; n < TN; n++) {
            unsigned int ul, uh;
            UNPACK2(ul, uh, acc2[m][n]);
            lo[n] = __uint_as_float(ul);
            hi[n] = __uint_as_float(uh);
        }
        if (r0 < M) {
#pragma unroll
            for (int n = 0; n < TN; n += 4)
                *(float4*)(C + (size_t)r0 * N + nBase + tx * TN + n) =
                    make_float4(lo[n], lo[n + 1], lo[n + 2], lo[n + 3]);
        }
        if (r0 + 1 < M) {
#pragma unroll
            for (int n = 0; n < TN; n += 4)
                *(float4*)(C + (size_t)(r0 + 1) * N + nBase + tx * TN + n) =
                    make_float4(hi[n], hi[n + 1], hi[n + 2], hi[n + 3]);
        }
    }
}

// ---------------- layer-1 neighbor sum only (needs y1 + CSR, NOT z1) --------
__global__ void gather1_sum_kernel() {
    int node = (blockIdx.x * blockDim.x + threadIdx.x) >> 5;  // warp per node
    if (node >= N_NODES) return;
    int lane = threadIdx.x & 31;

    int start = g_start[node];
    int deg   = g_deg[node];

    float4 acc = make_float4(0.f, 0.f, 0.f, 0.f);
    for (int e0 = 0; e0 < deg; e0 += 32) {
        int m = min(32, deg - e0);
        int myidx = e0 + lane;
        int s = (myidx < deg) ? g_csr[start + myidx] : 0;
        for (int j = 0; j < m; j++) {
            int src = __shfl_sync(0xFFFFFFFFu, s, j);
            float4 v = ((const float4*)g_y1)[(size_t)src * 32 + lane];
            acc.x += v.x; acc.y += v.y; acc.z += v.z; acc.w += v.w;
        }
    }
    ((float4*)g_h1)[(size_t)node * 32 + lane] = acc;   // raw sum
}

// ---------------- layer-1 epilogue: h1 = relu(sum/deg + z1 + b1) ------------
__global__ void epi1_kernel(const float* __restrict__ b1) {
    int idx = blockIdx.x * blockDim.x + threadIdx.x;   // float4 idx over N_NODES*32
    if (idx >= N_NODES * 32) return;
    int node = idx >> 5;
    int c4   = idx & 31;
    int deg  = g_deg[node];
    float inv = (deg > 0) ? 1.0f / (float)deg : 0.0f;
    float4 a = ((const float4*)g_h1)[idx];
    float4 z = ((const float4*)g_z1)[idx];
    float4 bb = ((const float4*)b1)[c4];
    float4 r;
    r.x = fmaxf(fmaf(a.x, inv, z.x + bb.x), 0.f);
    r.y = fmaxf(fmaf(a.y, inv, z.y + bb.y), 0.f);
    r.z = fmaxf(fmaf(a.z, inv, z.z + bb.z), 0.f);
    r.w = fmaxf(fmaf(a.w, inv, z.w + bb.w), 0.f);
    ((float4*)g_h1)[idx] = r;
}

// ---------------- layer-2 gather + log_softmax, fully fused ----------------
__global__ void gather2_kernel(const float* __restrict__ b2, float* __restrict__ out) {
    int node = (blockIdx.x * blockDim.x + threadIdx.x) >> 5;  // warp per node
    if (node >= N_NODES) return;
    int lane = threadIdx.x & 31;

    int start = g_start[node];
    int deg   = g_deg[node];

    float acc = 0.f;
    for (int e0 = 0; e0 < deg; e0 += 32) {
        int m = min(32, deg - e0);
        int myidx = e0 + lane;
        int s = (myidx < deg) ? g_csr[start + myidx] : 0;
        for (int j = 0; j < m; j++) {
            int src = __shfl_sync(0xFFFFFFFFu, s, j);
            acc += g_yz2[(size_t)src * 64 + lane];
        }
    }
    float inv = (deg > 0) ? 1.0f / (float)deg : 0.0f;
    float v = fmaf(acc, inv, g_yz2[(size_t)node * 64 + 32 + lane] + b2[lane]);

    float mx = v;
#pragma unroll
    for (int o = 16; o > 0; o >>= 1) mx = fmaxf(mx, __shfl_xor_sync(0xFFFFFFFFu, mx, o));
    float ex = expf(v - mx);
    float s = ex;
#pragma unroll
    for (int o = 16; o > 0; o >>= 1) s += __shfl_xor_sync(0xFFFFFFFFu, s, o);
    out[(size_t)node * 32 + lane] = v - mx - logf(s);
}

// ---------------- launch ----------------
extern "C" void kernel_launch(void* const* d_in, const int* in_sizes, int n_in,
                              void* d_out, int out_size) {
    const float* x   = (const float*)d_in[0];
    const void*  ei  = d_in[1];
    const float* W1l = (const float*)d_in[2];
    const float* W1r = (const float*)d_in[3];
    const float* b1  = (const float*)d_in[4];
    const float* W2l = (const float*)d_in[5];
    const float* W2r = (const float*)d_in[6];
    const float* b2  = (const float*)d_in[7];
    float* out = (float*)d_out;

    float *p_y1, *p_z1, *p_h1, *p_yz2, *p_W1a, *p_W1b, *p_W2;
    cudaGetSymbolAddress((void**)&p_y1,  g_y1);
    cudaGetSymbolAddress((void**)&p_z1,  g_z1);
    cudaGetSymbolAddress((void**)&p_h1,  g_h1);
    cudaGetSymbolAddress((void**)&p_yz2, g_yz2);
    cudaGetSymbolAddress((void**)&p_W1a, g_W1a);
    cudaGetSymbolAddress((void**)&p_W1b, g_W1b);
    cudaGetSymbolAddress((void**)&p_W2,  g_W2);

    static cudaStream_t s2 = nullptr, s3 = nullptr;
    static cudaEvent_t evFork = nullptr, evCSR = nullptr, evY = nullptr, evZ = nullptr;
    if (!s2) {
        cudaStreamCreateWithFlags(&s2, cudaStreamNonBlocking);
        cudaStreamCreateWithFlags(&s3, cudaStreamNonBlocking);
        cudaEventCreateWithFlags(&evFork, cudaEventDisableTiming);
        cudaEventCreateWithFlags(&evCSR,  cudaEventDisableTiming);
        cudaEventCreateWithFlags(&evY,    cudaEventDisableTiming);
        cudaEventCreateWithFlags(&evZ,    cudaEventDisableTiming);
    }

    detect_kernel<<<1, 32>>>(ei);
    setup_kernel<<<(N_NODES + 255) / 256, 256>>>(W1l, W1r, W2l, W2r);

    // fork: CSR build on s2 (L2/atomic-bound) under GEMM1y (FMA-bound)
    cudaEventRecord(evFork, 0);
    cudaStreamWaitEvent(s2, evFork, 0);

    convert_count_kernel<<<(N_EDGES + 255) / 256, 256, 0, s2>>>(ei);
    scanA_kernel<<<N_SCAN_BLOCKS, SCAN_BLK, 0, s2>>>();
    scanB_kernel<<<1, 64, 0, s2>>>();
    scanC_kernel<<<N_SCAN_BLOCKS, SCAN_BLK, 0, s2>>>();
    fill_kernel<<<(N_EDGES + 255) / 256, 256, 0, s2>>>();
    cudaEventRecord(evCSR, s2);

    // y1 = x @ W1l  (M=50000, K=128, N=128) — main stream
    {
        dim3 grid((N_NODES + 127) / 128, 1);
        sgemm_k128<128, 8><<<grid, 256>>>(x, p_W1a, p_y1, N_NODES, 128);
    }
    cudaEventRecord(evY, 0);

    // z1 = x @ W1r on s3, concurrent with gather1_sum (different pipes)
    cudaStreamWaitEvent(s3, evY, 0);
    {
        dim3 grid((N_NODES + 127) / 128, 1);
        sgemm_k128<128, 8><<<grid, 256, 0, s3>>>(x, p_W1b, p_z1, N_NODES, 128);
    }
    cudaEventRecord(evZ, s3);

    // gather1 sum (needs y1 + CSR)
    cudaStreamWaitEvent(0, evCSR, 0);
    gather1_sum_kernel<<<(N_NODES * 32 + 255) / 256, 256>>>();

    // epilogue (needs z1)
    cudaStreamWaitEvent(0, evZ, 0);
    epi1_kernel<<<(N_NODES * 32 + 255) / 256, 256>>>(b1);

    // yz2 = h1 @ [W2l | W2r]  (M=50000, K=128, N=64)
    {
        dim3 grid((N_NODES + 127) / 128, 1);
        sgemm_k128<64, 4><<<grid, 256>>>(p_h1, p_W2, p_yz2, N_NODES, 64);
    }
    gather2_kernel<<<(N_NODES * 32 + 255) / 256, 256>>>(b2, out);
}

// round 11
// speedup vs baseline: 1.7950x; 1.4018x over previous
#include <cuda_runtime.h>
#include <cstdint>

#define N_NODES 50000
#define N_EDGES 800000
#define SCAN_BLK 1024
#define N_SCAN_BLOCKS ((N_NODES + SCAN_BLK - 1) / SCAN_BLK)   // 49
#define M_TILES ((N_NODES + 127) / 128)                        // 391
#define LDS_PAD 132                                            // 128 + 4 floats

// ---------------- scratch (no allocation allowed; 16B aligned) ----------------
__device__ __align__(16) float g_y1 [N_NODES * 128];   // x @ W1l
__device__ __align__(16) float g_z1 [N_NODES * 128];   // x @ W1r
__device__ __align__(16) float g_h1 [N_NODES * 128];   // neighbor sum -> relu hidden
__device__ __align__(16) float g_yz2[N_NODES * 64];    // [y2 | z2] = h1 @ [W2l|W2r]
__device__ __align__(16) float g_W2 [128 * 64];        // [W2l | W2r], K x 64
__device__ __align__(16) int   g_deg  [N_NODES];
__device__ __align__(16) int   g_start[N_NODES];
__device__ __align__(16) int   g_fill [N_NODES];
__device__ __align__(16) int   g_csr  [N_EDGES];
__device__ __align__(16) int   g_blksum[64];
__device__ __align__(16) int   g_blkoff[64];
__device__ int g_is64;

__device__ __forceinline__ uint32_t f2tf32(float f) {
    uint32_t r;
    asm("cvt.rna.tf32.f32 %0, %1;" : "=r"(r) : "f"(f));
    return r;
}
__device__ __forceinline__ void mma_tf32(float* c, const uint32_t* a, const uint32_t* b) {
    asm("mma.sync.aligned.m16n8k8.row.col.f32.tf32.tf32.f32 "
        "{%0,%1,%2,%3}, {%4,%5,%6,%7}, {%8,%9}, {%0,%1,%2,%3};"
        : "+f"(c[0]), "+f"(c[1]), "+f"(c[2]), "+f"(c[3])
        : "r"(a[0]), "r"(a[1]), "r"(a[2]), "r"(a[3]), "r"(b[0]), "r"(b[1]));
}

// ---------------- dtype detect ----------------
__global__ void detect_kernel(const void* ei) {
    if (blockIdx.x | threadIdx.x) return;
    const long long* p = (const long long*)ei;
    int ok = 1;
    const int stride = N_EDGES / 64;
#pragma unroll 1
    for (int i = 0; i < 64; i++) {
        long long v = p[i * stride];
        if (v < 0 || v >= N_NODES) { ok = 0; break; }
    }
    g_is64 = ok;
}

// ---------------- setup: zero deg/fill + pack W2 ----------------
__global__ void setup_kernel(const float* __restrict__ W2l, const float* __restrict__ W2r) {
    int tid = blockIdx.x * blockDim.x + threadIdx.x;
    if (tid < N_NODES) { g_deg[tid] = 0; g_fill[tid] = 0; }
    if (tid < 128 * 64) {
        int k = tid >> 6, n = tid & 63;
        g_W2[tid] = (n < 32) ? W2l[k * 32 + n] : W2r[k * 32 + (n - 32)];
    }
}

// ---------------- degree count ----------------
__global__ void count_kernel(const void* ei) {
    int e = blockIdx.x * blockDim.x + threadIdx.x;
    if (e >= N_EDGES) return;
    int d = g_is64 ? (int)((const long long*)ei)[N_EDGES + e]
                   : ((const int*)ei)[N_EDGES + e];
    d = min(max(d, 0), N_NODES - 1);
    atomicAdd(&g_deg[d], 1);
}

// ---------------- parallel scan ----------------
__global__ void __launch_bounds__(SCAN_BLK) scanA_kernel() {
    __shared__ int wsum[32];
    int tid = threadIdx.x, lane = tid & 31, wid = tid >> 5;
    int i = blockIdx.x * SCAN_BLK + tid;
    int v = (i < N_NODES) ? g_deg[i] : 0;
    int inc = v;
#pragma unroll
    for (int o = 1; o < 32; o <<= 1) {
        int t = __shfl_up_sync(0xFFFFFFFFu, inc, o);
        if (lane >= o) inc += t;
    }
    if (lane == 31) wsum[wid] = inc;
    __syncthreads();
    if (wid == 0) {
        int s = wsum[lane];
#pragma unroll
        for (int o = 1; o < 32; o <<= 1) {
            int t = __shfl_up_sync(0xFFFFFFFFu, s, o);
            if (lane >= o) s += t;
        }
        wsum[lane] = s;
    }
    __syncthreads();
    int woff = wid ? wsum[wid - 1] : 0;
    if (i < N_NODES) g_start[i] = woff + inc - v;
    if (tid == SCAN_BLK - 1) g_blksum[blockIdx.x] = wsum[31];
}

__global__ void scanB_kernel() {
    __shared__ int sh[64];
    int t = threadIdx.x;
    sh[t] = (t < N_SCAN_BLOCKS) ? g_blksum[t] : 0;
    __syncthreads();
#pragma unroll
    for (int o = 1; o < 64; o <<= 1) {
        int v = (t >= o) ? sh[t - o] : 0;
        __syncthreads();
        sh[t] += v;
        __syncthreads();
    }
    if (t < N_SCAN_BLOCKS) g_blkoff[t] = sh[t] - g_blksum[t];
}

__global__ void __launch_bounds__(SCAN_BLK) scanC_kernel() {
    int i = blockIdx.x * SCAN_BLK + threadIdx.x;
    if (i < N_NODES) g_start[i] += g_blkoff[blockIdx.x];
}

// ---------------- CSR fill ----------------
__global__ void fill_kernel(const void* ei) {
    int e = blockIdx.x * blockDim.x + threadIdx.x;
    if (e >= N_EDGES) return;
    int s, d;
    if (g_is64) {
        const long long* p = (const long long*)ei;
        s = (int)p[e]; d = (int)p[N_EDGES + e];
    } else {
        const int* p = (const int*)ei;
        s = p[e]; d = p[N_EDGES + e];
    }
    s = min(max(s, 0), N_NODES - 1);
    d = min(max(d, 0), N_NODES - 1);
    int pos = g_start[d] + atomicAdd(&g_fill[d], 1);
    g_csr[pos] = s;
}

// ---------------- tf32 mma.sync GEMM: C[M x NT] = A[M x 128] @ W[128 x NT] ----
// 256 threads, BM=128, full K=128 staged once. A -> As[row][k], W -> Bs[n][k],
// both padded stride LDS_PAD for conflict-free fragment gathers.
template <int NT>
__global__ void __launch_bounds__(256)
mma_gemm(const float* __restrict__ A, const float* __restrict__ W,
         float* __restrict__ C, int M) {
    constexpr int WN = (NT == 128) ? 64 : 32;   // warp n-extent
    constexpr int NTILES = WN / 8;
    extern __shared__ float sm[];
    float* As = sm;                    // [128][LDS_PAD]
    float* Bs = sm + 128 * LDS_PAD;    // [NT][LDS_PAD]

    int tid = threadIdx.x, lane = tid & 31, wid = tid >> 5;
    int mBase = blockIdx.x * 128;

    // A tile: float4 coalesced, cvt.rna to tf32 bit pattern
#pragma unroll
    for (int it = 0; it < 16; it++) {
        int idx = tid + it * 256;       // float4 idx over 128x32
        int row = idx >> 5, c4 = idx & 31;
        float4 v = make_float4(0.f, 0.f, 0.f, 0.f);
        if (mBase + row < M)
            v = *(const float4*)(A + (size_t)(mBase + row) * 128 + c4 * 4);
        float* dst = As + row * LDS_PAD + c4 * 4;
        dst[0] = __uint_as_float(f2tf32(v.x));
        dst[1] = __uint_as_float(f2tf32(v.y));
        dst[2] = __uint_as_float(f2tf32(v.z));
        dst[3] = __uint_as_float(f2tf32(v.w));
    }
    // B tile: W row-major [k][n] -> Bs[n][k]; global index linear = coalesced
#pragma unroll
    for (int it = 0; it < (NT * 128) / 256; it++) {
        int idx = tid + it * 256;
        int n = idx % NT, k = idx / NT;
        Bs[n * LDS_PAD + k] = __uint_as_float(f2tf32(W[idx]));
    }
    __syncthreads();

    int warp_m = wid & 3;       // 4 m-slices x 32 rows
    int warp_n = wid >> 2;      // 2 n-slices x WN cols
    int r = lane >> 2, q = lane & 3;

    float acc[2][NTILES][4];
#pragma unroll
    for (int tm = 0; tm < 2; tm++)
#pragma unroll
        for (int tn = 0; tn < NTILES; tn++)
#pragma unroll
            for (int i = 0; i < 4; i++) acc[tm][tn][i] = 0.f;

#pragma unroll
    for (int k0 = 0; k0 < 128; k0 += 8) {
        uint32_t a[2][4];
#pragma unroll
        for (int tm = 0; tm < 2; tm++) {
            const float* base = As + (warp_m * 32 + tm * 16 + r) * LDS_PAD + k0;
            a[tm][0] = __float_as_uint(base[q]);
            a[tm][1] = __float_as_uint(base[8 * LDS_PAD + q]);
            a[tm][2] = __float_as_uint(base[q + 4]);
            a[tm][3] = __float_as_uint(base[8 * LDS_PAD + q + 4]);
        }
        uint32_t b[NTILES][2];
#pragma unroll
        for (int tn = 0; tn < NTILES; tn++) {
            const float* base = Bs + (warp_n * WN + tn * 8 + r) * LDS_PAD + k0;
            b[tn][0] = __float_as_uint(base[q]);
            b[tn][1] = __float_as_uint(base[q + 4]);
        }
#pragma unroll
        for (int tm = 0; tm < 2; tm++)
#pragma unroll
            for (int tn = 0; tn < NTILES; tn++)
                mma_tf32(acc[tm][tn], a[tm], b[tn]);
    }

    // writeout: c0,c1 at (row, 2q), (row, 2q+1); c2,c3 at row+8
#pragma unroll
    for (int tm = 0; tm < 2; tm++) {
        int row0 = mBase + warp_m * 32 + tm * 16 + r;
#pragma unroll
        for (int tn = 0; tn < NTILES; tn++) {
            int col = warp_n * WN + tn * 8 + 2 * q;
            if (row0 < M)
                *(float2*)(C + (size_t)row0 * NT + col) =
                    make_float2(acc[tm][tn][0], acc[tm][tn][1]);
            if (row0 + 8 < M)
                *(float2*)(C + (size_t)(row0 + 8) * NT + col) =
                    make_float2(acc[tm][tn][2], acc[tm][tn][3]);
        }
    }
}

// ---------------- layer-1 neighbor sum (needs y1 + CSR) ----------------
__global__ void gather1_sum_kernel() {
    int node = (blockIdx.x * blockDim.x + threadIdx.x) >> 5;
    if (node >= N_NODES) return;
    int lane = threadIdx.x & 31;
    int start = g_start[node];
    int deg   = g_deg[node];

    float4 acc = make_float4(0.f, 0.f, 0.f, 0.f);
    for (int e0 = 0; e0 < deg; e0 += 32) {
        int m = min(32, deg - e0);
        int myidx = e0 + lane;
        int s = (myidx < deg) ? g_csr[start + myidx] : 0;
        for (int j = 0; j < m; j++) {
            int src = __shfl_sync(0xFFFFFFFFu, s, j);
            float4 v = ((const float4*)g_y1)[(size_t)src * 32 + lane];
            acc.x += v.x; acc.y += v.y; acc.z += v.z; acc.w += v.w;
        }
    }
    ((float4*)g_h1)[(size_t)node * 32 + lane] = acc;
}

// ---------------- layer-1 epilogue: h1 = relu(sum/deg + z1 + b1) ------------
__global__ void epi1_kernel(const float* __restrict__ b1) {
    int idx = blockIdx.x * blockDim.x + threadIdx.x;
    if (idx >= N_NODES * 32) return;
    int node = idx >> 5;
    int c4   = idx & 31;
    int deg  = g_deg[node];
    float inv = (deg > 0) ? 1.0f / (float)deg : 0.0f;
    float4 a = ((const float4*)g_h1)[idx];
    float4 z = ((const float4*)g_z1)[idx];
    float4 bb = ((const float4*)b1)[c4];
    float4 r;
    r.x = fmaxf(fmaf(a.x, inv, z.x + bb.x), 0.f);
    r.y = fmaxf(fmaf(a.y, inv, z.y + bb.y), 0.f);
    r.z = fmaxf(fmaf(a.z, inv, z.z + bb.z), 0.f);
    r.w = fmaxf(fmaf(a.w, inv, z.w + bb.w), 0.f);
    ((float4*)g_h1)[idx] = r;
}

// ---------------- layer-2 gather + log_softmax ----------------
__global__ void gather2_kernel(const float* __restrict__ b2, float* __restrict__ out) {
    int node = (blockIdx.x * blockDim.x + threadIdx.x) >> 5;
    if (node >= N_NODES) return;
    int lane = threadIdx.x & 31;
    int start = g_start[node];
    int deg   = g_deg[node];

    float acc = 0.f;
    for (int e0 = 0; e0 < deg; e0 += 32) {
        int m = min(32, deg - e0);
        int myidx = e0 + lane;
        int s = (myidx < deg) ? g_csr[start + myidx] : 0;
        for (int j = 0; j < m; j++) {
            int src = __shfl_sync(0xFFFFFFFFu, s, j);
            acc += g_yz2[(size_t)src * 64 + lane];
        }
    }
    float inv = (deg > 0) ? 1.0f / (float)deg : 0.0f;
    float v = fmaf(acc, inv, g_yz2[(size_t)node * 64 + 32 + lane] + b2[lane]);

    float mx = v;
#pragma unroll
    for (int o = 16; o > 0; o >>= 1) mx = fmaxf(mx, __shfl_xor_sync(0xFFFFFFFFu, mx, o));
    float ex = expf(v - mx);
    float s = ex;
#pragma unroll
    for (int o = 16; o > 0; o >>= 1) s += __shfl_xor_sync(0xFFFFFFFFu, s, o);
    out[(size_t)node * 32 + lane] = v - mx - logf(s);
}

// ---------------- launch ----------------
extern "C" void kernel_launch(void* const* d_in, const int* in_sizes, int n_in,
                              void* d_out, int out_size) {
    const float* x   = (const float*)d_in[0];
    const void*  ei  = d_in[1];
    const float* W1l = (const float*)d_in[2];
    const float* W1r = (const float*)d_in[3];
    const float* b1  = (const float*)d_in[4];
    const float* W2l = (const float*)d_in[5];
    const float* W2r = (const float*)d_in[6];
    const float* b2  = (const float*)d_in[7];
    float* out = (float*)d_out;

    float *p_y1, *p_z1, *p_h1, *p_yz2, *p_W2;
    cudaGetSymbolAddress((void**)&p_y1,  g_y1);
    cudaGetSymbolAddress((void**)&p_z1,  g_z1);
    cudaGetSymbolAddress((void**)&p_h1,  g_h1);
    cudaGetSymbolAddress((void**)&p_yz2, g_yz2);
    cudaGetSymbolAddress((void**)&p_W2,  g_W2);

    const int SMEM1 = (128 + 128) * LDS_PAD * 4;   // 135168 B
    const int SMEM2 = (128 + 64)  * LDS_PAD * 4;   // 101376 B
    cudaFuncSetAttribute(mma_gemm<128>, cudaFuncAttributeMaxDynamicSharedMemorySize, SMEM1);
    cudaFuncSetAttribute(mma_gemm<64>,  cudaFuncAttributeMaxDynamicSharedMemorySize, SMEM2);

    static cudaStream_t s2 = nullptr, s3 = nullptr;
    static cudaEvent_t evFork = nullptr, evCSR = nullptr, evY = nullptr, evZ = nullptr;
    if (!s2) {
        cudaStreamCreateWithFlags(&s2, cudaStreamNonBlocking);
        cudaStreamCreateWithFlags(&s3, cudaStreamNonBlocking);
        cudaEventCreateWithFlags(&evFork, cudaEventDisableTiming);
        cudaEventCreateWithFlags(&evCSR,  cudaEventDisableTiming);
        cudaEventCreateWithFlags(&evY,    cudaEventDisableTiming);
        cudaEventCreateWithFlags(&evZ,    cudaEventDisableTiming);
    }

    detect_kernel<<<1, 32>>>(ei);
    setup_kernel<<<(N_NODES + 255) / 256, 256>>>(W2l, W2r);

    // fork: CSR build on s2
    cudaEventRecord(evFork, 0);
    cudaStreamWaitEvent(s2, evFork, 0);
    count_kernel<<<(N_EDGES + 255) / 256, 256, 0, s2>>>(ei);
    scanA_kernel<<<N_SCAN_BLOCKS, SCAN_BLK, 0, s2>>>();
    scanB_kernel<<<1, 64, 0, s2>>>();
    scanC_kernel<<<N_SCAN_BLOCKS, SCAN_BLK, 0, s2>>>();
    fill_kernel<<<(N_EDGES + 255) / 256, 256, 0, s2>>>(ei);
    cudaEventRecord(evCSR, s2);

    // y1 = x @ W1l (tf32 mma.sync) — main stream
    mma_gemm<128><<<M_TILES, 256, SMEM1>>>(x, W1l, p_y1, N_NODES);
    cudaEventRecord(evY, 0);

    // z1 = x @ W1r on s3, concurrent with gather1_sum
    cudaStreamWaitEvent(s3, evY, 0);
    mma_gemm<128><<<M_TILES, 256, SMEM1, s3>>>(x, W1r, p_z1, N_NODES);
    cudaEventRecord(evZ, s3);

    // gather1 sum (needs y1 + CSR)
    cudaStreamWaitEvent(0, evCSR, 0);
    gather1_sum_kernel<<<(N_NODES * 32 + 255) / 256, 256>>>();

    // epilogue (needs z1)
    cudaStreamWaitEvent(0, evZ, 0);
    epi1_kernel<<<(N_NODES * 32 + 255) / 256, 256>>>(b1);

    // yz2 = h1 @ [W2l | W2r] (tf32 mma.sync, N=64)
    mma_gemm<64><<<M_TILES, 256, SMEM2>>>(p_h1, p_W2, p_yz2, N_NODES);
    gather2_kernel<<<(N_NODES * 32 + 255) / 256, 256>>>(b2, out);
}

// round 12
// speedup vs baseline: 1.8453x; 1.0280x over previous
#include <cuda_runtime.h>
#include <cstdint>

#define N_NODES 50000
#define N_EDGES 800000
#define SCAN_BLK 1024
#define N_SCAN_BLOCKS ((N_NODES + SCAN_BLK - 1) / SCAN_BLK)   // 49
#define M_TILES ((N_NODES + 127) / 128)                        // 391
#define LDS_PAD 132                                            // 128 + 4 floats

// ---------------- scratch (no allocation allowed; 16B aligned) ----------------
__device__ __align__(16) float g_y1 [N_NODES * 128];   // x @ W1l
__device__ __align__(16) float g_z1 [N_NODES * 128];   // x @ W1r
__device__ __align__(16) float g_h1 [N_NODES * 128];   // relu hidden
__device__ __align__(16) float g_yz2[N_NODES * 64];    // [y2 | z2] = h1 @ [W2l|W2r]
__device__ __align__(16) float g_W2 [128 * 64];        // [W2l | W2r], K x 64
__device__ __align__(16) int   g_deg  [N_NODES];
__device__ __align__(16) int   g_start[N_NODES];       // block-LOCAL exclusive scan
__device__ __align__(16) int   g_fill [N_NODES];
__device__ __align__(16) int   g_csr  [N_EDGES];
__device__ __align__(16) int   g_blksum[64];
__device__ __align__(16) int   g_blkoff[64];           // block offsets (added on use)
__device__ int g_is64;

__device__ __forceinline__ uint32_t f2tf32(float f) {
    uint32_t r;
    asm("cvt.rna.tf32.f32 %0, %1;" : "=r"(r) : "f"(f));
    return r;
}
__device__ __forceinline__ void mma_tf32(float* c, const uint32_t* a, const uint32_t* b) {
    asm("mma.sync.aligned.m16n8k8.row.col.f32.tf32.tf32.f32 "
        "{%0,%1,%2,%3}, {%4,%5,%6,%7}, {%8,%9}, {%0,%1,%2,%3};"
        : "+f"(c[0]), "+f"(c[1]), "+f"(c[2]), "+f"(c[3])
        : "r"(a[0]), "r"(a[1]), "r"(a[2]), "r"(a[3]), "r"(b[0]), "r"(b[1]));
}

// ---------------- dtype detect (1 warp, parallel samples + ballot) ----------
__global__ void detect_kernel(const void* ei) {
    int lane = threadIdx.x;
    const long long* p = (const long long*)ei;
    const int stride = N_EDGES / 64;
    int ok = 1;
#pragma unroll
    for (int i = 0; i < 2; i++) {
        long long v = p[(lane + i * 32) * stride];
        if (v < 0 || v >= N_NODES) ok = 0;
    }
    ok = __all_sync(0xFFFFFFFFu, ok);
    if (lane == 0) g_is64 = ok;
}

// ---------------- setup: zero deg/fill + pack W2 ----------------
__global__ void setup_kernel(const float* __restrict__ W2l, const float* __restrict__ W2r) {
    int tid = blockIdx.x * blockDim.x + threadIdx.x;
    if (tid < N_NODES) { g_deg[tid] = 0; g_fill[tid] = 0; }
    if (tid < 128 * 64) {
        int k = tid >> 6, n = tid & 63;
        g_W2[tid] = (n < 32) ? W2l[k * 32 + n] : W2r[k * 32 + (n - 32)];
    }
}

// ---------------- degree count ----------------
__global__ void count_kernel(const void* ei) {
    int e = blockIdx.x * blockDim.x + threadIdx.x;
    if (e >= N_EDGES) return;
    int d = g_is64 ? (int)((const long long*)ei)[N_EDGES + e]
                   : ((const int*)ei)[N_EDGES + e];
    d = min(max(d, 0), N_NODES - 1);
    atomicAdd(&g_deg[d], 1);
}

// ---------------- parallel scan (A: per-block local; B: block totals) --------
__global__ void __launch_bounds__(SCAN_BLK) scanA_kernel() {
    __shared__ int wsum[32];
    int tid = threadIdx.x, lane = tid & 31, wid = tid >> 5;
    int i = blockIdx.x * SCAN_BLK + tid;
    int v = (i < N_NODES) ? g_deg[i] : 0;
    int inc = v;
#pragma unroll
    for (int o = 1; o < 32; o <<= 1) {
        int t = __shfl_up_sync(0xFFFFFFFFu, inc, o);
        if (lane >= o) inc += t;
    }
    if (lane == 31) wsum[wid] = inc;
    __syncthreads();
    if (wid == 0) {
        int s = wsum[lane];
#pragma unroll
        for (int o = 1; o < 32; o <<= 1) {
            int t = __shfl_up_sync(0xFFFFFFFFu, s, o);
            if (lane >= o) s += t;
        }
        wsum[lane] = s;
    }
    __syncthreads();
    int woff = wid ? wsum[wid - 1] : 0;
    if (i < N_NODES) g_start[i] = woff + inc - v;
    if (tid == SCAN_BLK - 1) g_blksum[blockIdx.x] = wsum[31];
}

__global__ void scanB_kernel() {
    __shared__ int sh[64];
    int t = threadIdx.x;
    sh[t] = (t < N_SCAN_BLOCKS) ? g_blksum[t] : 0;
    __syncthreads();
#pragma unroll
    for (int o = 1; o < 64; o <<= 1) {
        int v = (t >= o) ? sh[t - o] : 0;
        __syncthreads();
        sh[t] += v;
        __syncthreads();
    }
    if (t < N_SCAN_BLOCKS) g_blkoff[t] = sh[t] - g_blksum[t];
}

// ---------------- CSR fill (adds block offset inline) ----------------
__global__ void fill_kernel(const void* ei) {
    int e = blockIdx.x * blockDim.x + threadIdx.x;
    if (e >= N_EDGES) return;
    int s, d;
    if (g_is64) {
        const long long* p = (const long long*)ei;
        s = (int)p[e]; d = (int)p[N_EDGES + e];
    } else {
        const int* p = (const int*)ei;
        s = p[e]; d = p[N_EDGES + e];
    }
    s = min(max(s, 0), N_NODES - 1);
    d = min(max(d, 0), N_NODES - 1);
    int pos = g_start[d] + g_blkoff[d >> 10] + atomicAdd(&g_fill[d], 1);
    g_csr[pos] = s;
}

// ---------------- tf32 mma.sync GEMM body: C[128 rows x NT] = A @ W ----------
template <int NT>
__device__ __forceinline__ void mma_gemm_body(
    const float* __restrict__ A, const float* __restrict__ W,
    float* __restrict__ C, int M) {
    constexpr int WN = (NT == 128) ? 64 : 32;
    constexpr int NTILES = WN / 8;
    extern __shared__ float sm[];
    float* As = sm;                    // [128][LDS_PAD]
    float* Bs = sm + 128 * LDS_PAD;    // [NT][LDS_PAD]

    int tid = threadIdx.x, lane = tid & 31, wid = tid >> 5;
    int mBase = blockIdx.x * 128;

#pragma unroll
    for (int it = 0; it < 16; it++) {
        int idx = tid + it * 256;
        int row = idx >> 5, c4 = idx & 31;
        float4 v = make_float4(0.f, 0.f, 0.f, 0.f);
        if (mBase + row < M)
            v = *(const float4*)(A + (size_t)(mBase + row) * 128 + c4 * 4);
        float* dst = As + row * LDS_PAD + c4 * 4;
        dst[0] = __uint_as_float(f2tf32(v.x));
        dst[1] = __uint_as_float(f2tf32(v.y));
        dst[2] = __uint_as_float(f2tf32(v.z));
        dst[3] = __uint_as_float(f2tf32(v.w));
    }
#pragma unroll
    for (int it = 0; it < (NT * 128) / 256; it++) {
        int idx = tid + it * 256;
        int n = idx % NT, k = idx / NT;
        Bs[n * LDS_PAD + k] = __uint_as_float(f2tf32(W[idx]));
    }
    __syncthreads();

    int warp_m = wid & 3;
    int warp_n = wid >> 2;
    int r = lane >> 2, q = lane & 3;

    float acc[2][NTILES][4];
#pragma unroll
    for (int tm = 0; tm < 2; tm++)
#pragma unroll
        for (int tn = 0; tn < NTILES; tn++)
#pragma unroll
            for (int i = 0; i < 4; i++) acc[tm][tn][i] = 0.f;

#pragma unroll
    for (int k0 = 0; k0 < 128; k0 += 8) {
        uint32_t a[2][4];
#pragma unroll
        for (int tm = 0; tm < 2; tm++) {
            const float* base = As + (warp_m * 32 + tm * 16 + r) * LDS_PAD + k0;
            a[tm][0] = __float_as_uint(base[q]);
            a[tm][1] = __float_as_uint(base[8 * LDS_PAD + q]);
            a[tm][2] = __float_as_uint(base[q + 4]);
            a[tm][3] = __float_as_uint(base[8 * LDS_PAD + q + 4]);
        }
        uint32_t b[NTILES][2];
#pragma unroll
        for (int tn = 0; tn < NTILES; tn++) {
            const float* base = Bs + (warp_n * WN + tn * 8 + r) * LDS_PAD + k0;
            b[tn][0] = __float_as_uint(base[q]);
            b[tn][1] = __float_as_uint(base[q + 4]);
        }
#pragma unroll
        for (int tm = 0; tm < 2; tm++)
#pragma unroll
            for (int tn = 0; tn < NTILES; tn++)
                mma_tf32(acc[tm][tn], a[tm], b[tn]);
    }

#pragma unroll
    for (int tm = 0; tm < 2; tm++) {
        int row0 = mBase + warp_m * 32 + tm * 16 + r;
#pragma unroll
        for (int tn = 0; tn < NTILES; tn++) {
            int col = warp_n * WN + tn * 8 + 2 * q;
            if (row0 < M)
                *(float2*)(C + (size_t)row0 * NT + col) =
                    make_float2(acc[tm][tn][0], acc[tm][tn][1]);
            if (row0 + 8 < M)
                *(float2*)(C + (size_t)(row0 + 8) * NT + col) =
                    make_float2(acc[tm][tn][2], acc[tm][tn][3]);
        }
    }
}

// dual GEMM1: grid.y = 0 -> y1 = x@W1l ; grid.y = 1 -> z1 = x@W1r
__global__ void __launch_bounds__(256)
gemm1_kernel(const float* __restrict__ A,
             const float* __restrict__ W0, const float* __restrict__ W1,
             float* __restrict__ C0, float* __restrict__ C1, int M) {
    if (blockIdx.y == 0) mma_gemm_body<128>(A, W0, C0, M);
    else                 mma_gemm_body<128>(A, W1, C1, M);
}

__global__ void __launch_bounds__(256)
gemm2_kernel(const float* __restrict__ A, const float* __restrict__ W,
             float* __restrict__ C, int M) {
    mma_gemm_body<64>(A, W, C, M);
}

// ---------------- layer-1 gather + epilogue fused ----------------
// h1 = relu(sum(y1[src])/deg + z1 + b1); same stream after gemm1 => z1 ready.
__global__ void gather1_kernel(const float* __restrict__ b1) {
    int node = (blockIdx.x * blockDim.x + threadIdx.x) >> 5;
    if (node >= N_NODES) return;
    int lane = threadIdx.x & 31;
    int start = g_start[node] + g_blkoff[node >> 10];
    int deg   = g_deg[node];

    float4 acc = make_float4(0.f, 0.f, 0.f, 0.f);
    for (int e0 = 0; e0 < deg; e0 += 32) {
        int m = min(32, deg - e0);
        int myidx = e0 + lane;
        int s = (myidx < deg) ? g_csr[start + myidx] : 0;
        for (int j = 0; j < m; j++) {
            int src = __shfl_sync(0xFFFFFFFFu, s, j);
            float4 v = ((const float4*)g_y1)[(size_t)src * 32 + lane];
            acc.x += v.x; acc.y += v.y; acc.z += v.z; acc.w += v.w;
        }
    }
    float inv = (deg > 0) ? 1.0f / (float)deg : 0.0f;
    float4 z  = ((const float4*)g_z1)[(size_t)node * 32 + lane];
    float4 bb = ((const float4*)b1)[lane];
    float4 r;
    r.x = fmaxf(fmaf(acc.x, inv, z.x + bb.x), 0.f);
    r.y = fmaxf(fmaf(acc.y, inv, z.y + bb.y), 0.f);
    r.z = fmaxf(fmaf(acc.z, inv, z.z + bb.z), 0.f);
    r.w = fmaxf(fmaf(acc.w, inv, z.w + bb.w), 0.f);
    ((float4*)g_h1)[(size_t)node * 32 + lane] = r;
}

// ---------------- layer-2 gather + log_softmax ----------------
__global__ void gather2_kernel(const float* __restrict__ b2, float* __restrict__ out) {
    int node = (blockIdx.x * blockDim.x + threadIdx.x) >> 5;
    if (node >= N_NODES) return;
    int lane = threadIdx.x & 31;
    int start = g_start[node] + g_blkoff[node >> 10];
    int deg   = g_deg[node];

    float acc = 0.f;
    for (int e0 = 0; e0 < deg; e0 += 32) {
        int m = min(32, deg - e0);
        int myidx = e0 + lane;
        int s = (myidx < deg) ? g_csr[start + myidx] : 0;
        for (int j = 0; j < m; j++) {
            int src = __shfl_sync(0xFFFFFFFFu, s, j);
            acc += g_yz2[(size_t)src * 64 + lane];
        }
    }
    float inv = (deg > 0) ? 1.0f / (float)deg : 0.0f;
    float v = fmaf(acc, inv, g_yz2[(size_t)node * 64 + 32 + lane] + b2[lane]);

    float mx = v;
#pragma unroll
    for (int o = 16; o > 0; o >>= 1) mx = fmaxf(mx, __shfl_xor_sync(0xFFFFFFFFu, mx, o));
    float ex = expf(v - mx);
    float s = ex;
#pragma unroll
    for (int o = 16; o > 0; o >>= 1) s += __shfl_xor_sync(0xFFFFFFFFu, s, o);
    out[(size_t)node * 32 + lane] = v - mx - logf(s);
}

// ---------------- launch ----------------
extern "C" void kernel_launch(void* const* d_in, const int* in_sizes, int n_in,
                              void* d_out, int out_size) {
    const float* x   = (const float*)d_in[0];
    const void*  ei  = d_in[1];
    const float* W1l = (const float*)d_in[2];
    const float* W1r = (const float*)d_in[3];
    const float* b1  = (const float*)d_in[4];
    const float* W2l = (const float*)d_in[5];
    const float* W2r = (const float*)d_in[6];
    const float* b2  = (const float*)d_in[7];
    float* out = (float*)d_out;

    float *p_y1, *p_z1, *p_h1, *p_yz2, *p_W2;
    cudaGetSymbolAddress((void**)&p_y1,  g_y1);
    cudaGetSymbolAddress((void**)&p_z1,  g_z1);
    cudaGetSymbolAddress((void**)&p_h1,  g_h1);
    cudaGetSymbolAddress((void**)&p_yz2, g_yz2);
    cudaGetSymbolAddress((void**)&p_W2,  g_W2);

    const int SMEM1 = (128 + 128) * LDS_PAD * 4;   // 135168 B
    const int SMEM2 = (128 + 64)  * LDS_PAD * 4;   // 101376 B
    cudaFuncSetAttribute(gemm1_kernel, cudaFuncAttributeMaxDynamicSharedMemorySize, SMEM1);
    cudaFuncSetAttribute(gemm2_kernel, cudaFuncAttributeMaxDynamicSharedMemorySize, SMEM2);

    static cudaStream_t s2 = nullptr;
    static cudaEvent_t evFork = nullptr, evCSR = nullptr;
    if (!s2) {
        cudaStreamCreateWithFlags(&s2, cudaStreamNonBlocking);
        cudaEventCreateWithFlags(&evFork, cudaEventDisableTiming);
        cudaEventCreateWithFlags(&evCSR,  cudaEventDisableTiming);
    }

    detect_kernel<<<1, 32>>>(ei);

    // fork: CSR chain (setup -> count -> scanA -> scanB -> fill) on s2
    cudaEventRecord(evFork, 0);
    cudaStreamWaitEvent(s2, evFork, 0);
    setup_kernel<<<(N_NODES + 255) / 256, 256, 0, s2>>>(W2l, W2r);
    count_kernel<<<(N_EDGES + 255) / 256, 256, 0, s2>>>(ei);
    scanA_kernel<<<N_SCAN_BLOCKS, SCAN_BLK, 0, s2>>>();
    scanB_kernel<<<1, 64, 0, s2>>>();
    fill_kernel<<<(N_EDGES + 255) / 256, 256, 0, s2>>>(ei);
    cudaEventRecord(evCSR, s2);

    // y1 & z1 in one launch (grid.y = 2) — main stream, concurrent with CSR
    {
        dim3 grid(M_TILES, 2);
        gemm1_kernel<<<grid, 256, SMEM1>>>(x, W1l, W1r, p_y1, p_z1, N_NODES);
    }

    // gather1 (fused epilogue) needs CSR + y1 + z1
    cudaStreamWaitEvent(0, evCSR, 0);
    gather1_kernel<<<(N_NODES * 32 + 255) / 256, 256>>>(b1);

    // yz2 = h1 @ [W2l | W2r]
    gemm2_kernel<<<M_TILES, 256, SMEM2>>>(p_h1, p_W2, p_yz2, N_NODES);
    gather2_kernel<<<(N_NODES * 32 + 255) / 256, 256>>>(b2, out);
}